// round 2
// baseline (speedup 1.0000x reference)
#include <cuda_runtime.h>
#include <math.h>

#define BB 4
#define LL 4096
#define HIDN 1024
#define HH 16
#define DD 64
#define DMM 128
#define CSZ 64
#define NCH 64
#define MM (BB*LL)
#define EPSF 1e-6f

// ---------------- scratch (static device globals; no allocs allowed) ----------------
static __device__ float g_qkv [(size_t)3*MM*HIDN];        // raw q,k,v projections [3][M][1024]
static __device__ float g_proc[(size_t)3*BB*HH*LL*DD];    // processed q,k,v  [3][B*H][L][D]
static __device__ float g_gate[(size_t)3*BB*HH*LL];       // md, sd, lr       [3][B*H][L]

#define NPROC ((size_t)BB*HH*LL*DD)
#define NGATE ((size_t)BB*HH*LL)

__device__ __forceinline__ float sigmf(float x) {
    return __fdividef(1.0f, 1.0f + __expf(-x));
}

// ---------------- K1: qkv projection GEMM  C = X @ W^T ----------------
// BM=BN=64, BK=16, 256 threads, 4x4 per thread
__global__ void __launch_bounds__(256) k_qkv(
    const float* __restrict__ X,
    const float* __restrict__ Wq, const float* __restrict__ Wk, const float* __restrict__ Wv)
{
    __shared__ float As[16][68];
    __shared__ float Bs[16][68];
    const float* W = (blockIdx.z == 0) ? Wq : ((blockIdx.z == 1) ? Wk : Wv);
    float* C = g_qkv + (size_t)blockIdx.z * MM * HIDN;
    const int m0 = blockIdx.y * 64, n0 = blockIdx.x * 64;
    const int t = threadIdx.x;
    const int lr = t >> 2, lk = (t & 3) * 4;
    const int ty = t >> 4, tx = t & 15;
    float acc[4][4] = {};
    const float* Arow = X + (size_t)(m0 + lr) * HIDN + lk;
    const float* Brow = W + (size_t)(n0 + lr) * HIDN + lk;
    for (int k0 = 0; k0 < HIDN; k0 += 16) {
        float4 av = *(const float4*)(Arow + k0);
        float4 bv = *(const float4*)(Brow + k0);
        As[lk + 0][lr] = av.x; As[lk + 1][lr] = av.y; As[lk + 2][lr] = av.z; As[lk + 3][lr] = av.w;
        Bs[lk + 0][lr] = bv.x; Bs[lk + 1][lr] = bv.y; Bs[lk + 2][lr] = bv.z; Bs[lk + 3][lr] = bv.w;
        __syncthreads();
#pragma unroll
        for (int kk = 0; kk < 16; kk++) {
            float4 a = *(const float4*)&As[kk][ty * 4];
            float4 b = *(const float4*)&Bs[kk][tx * 4];
            float ar[4] = {a.x, a.y, a.z, a.w};
            float br[4] = {b.x, b.y, b.z, b.w};
#pragma unroll
            for (int i = 0; i < 4; i++)
#pragma unroll
                for (int j = 0; j < 4; j++) acc[i][j] += ar[i] * br[j];
        }
        __syncthreads();
    }
#pragma unroll
    for (int i = 0; i < 4; i++) {
        float4 o; o.x = acc[i][0]; o.y = acc[i][1]; o.z = acc[i][2]; o.w = acc[i][3];
        *(float4*)(C + (size_t)(m0 + ty * 4 + i) * HIDN + n0 + tx * 4) = o;
    }
}

// ---------------- K2: gate projections (N=48) + sigmoid transforms ----------------
// BM=64, BN=48, BK=16, 256 threads, 4x3 per thread
__global__ void __launch_bounds__(256) k_gate(
    const float* __restrict__ X,
    const float* __restrict__ mdw, const float* __restrict__ mdb,
    const float* __restrict__ sw,  const float* __restrict__ sb,
    const float* __restrict__ lw,  const float* __restrict__ lb)
{
    __shared__ float As[16][68];
    __shared__ float Bg[16][52];
    const int m0 = blockIdx.x * 64;
    const int t = threadIdx.x;
    const int lr = t >> 2, lk = (t & 3) * 4;
    const int ty = t >> 4, tx = t & 15;
    float acc[4][3] = {};
    const float* Arow = X + (size_t)(m0 + lr) * HIDN + lk;
    for (int k0 = 0; k0 < HIDN; k0 += 16) {
        float4 av = *(const float4*)(Arow + k0);
        As[lk + 0][lr] = av.x; As[lk + 1][lr] = av.y; As[lk + 2][lr] = av.z; As[lk + 3][lr] = av.w;
        if (t < 192) {
#pragma unroll
            for (int j = 0; j < 4; j++) {
                int idx = t * 4 + j;
                int n = idx >> 4, k = idx & 15;
                const float* wp = (n < 16) ? (mdw + (size_t)n * HIDN)
                                : (n < 32) ? (sw + (size_t)(n - 16) * HIDN)
                                           : (lw + (size_t)(n - 32) * HIDN);
                Bg[k][n] = wp[k0 + k];
            }
        }
        __syncthreads();
#pragma unroll
        for (int kk = 0; kk < 16; kk++) {
            float4 a = *(const float4*)&As[kk][ty * 4];
            float ar[4] = {a.x, a.y, a.z, a.w};
            float b0 = Bg[kk][tx * 3 + 0];
            float b1 = Bg[kk][tx * 3 + 1];
            float b2 = Bg[kk][tx * 3 + 2];
#pragma unroll
            for (int i = 0; i < 4; i++) {
                acc[i][0] += ar[i] * b0;
                acc[i][1] += ar[i] * b1;
                acc[i][2] += ar[i] * b2;
            }
        }
        __syncthreads();
    }
#pragma unroll
    for (int i = 0; i < 4; i++) {
#pragma unroll
        for (int j = 0; j < 3; j++) {
            int m = m0 + ty * 4 + i;
            int o = tx * 3 + j;
            float bias = (o < 16) ? mdb[o] : (o < 32) ? sb[o - 16] : lb[o - 32];
            float v = sigmf(acc[i][j] + bias);
            int bcur = m >> 12;           // m / L
            int l = m & (LL - 1);
            int g = o >> 4;
            int hh = o & 15;
            size_t gi = (size_t)g * NGATE + ((size_t)(bcur * HH + hh)) * LL + l;
            g_gate[gi] = (g == 0) ? (1.0f - v) : v;
        }
    }
}

// ---------------- K3: causal conv(K=4) + silu (+ rmsnorm for q,k) ----------------
// one block per (l, b, tensor z); 256 threads * 4 channels
__global__ void __launch_bounds__(256) k_conv(
    const float* __restrict__ cqw, const float* __restrict__ cqb,
    const float* __restrict__ ckw, const float* __restrict__ ckb,
    const float* __restrict__ cvw, const float* __restrict__ cvb,
    const float* __restrict__ qnw, const float* __restrict__ knw)
{
    const int z = blockIdx.z;
    const int b = blockIdx.y;
    const int l = blockIdx.x;
    const float* w    = (z == 0) ? cqw : (z == 1) ? ckw : cvw;
    const float* bias = (z == 0) ? cqb : (z == 1) ? ckb : cvb;
    const float* src = g_qkv + (size_t)z * MM * HIDN + (size_t)b * LL * HIDN;
    __shared__ float hs[16];
    const int t = threadIdx.x;
    if (t < 16) hs[t] = 0.0f;
    __syncthreads();
    const int c0 = t * 4;
    float y[4];
#pragma unroll
    for (int j = 0; j < 4; j++) y[j] = bias[c0 + j];
#pragma unroll
    for (int j = 0; j < 4; j++) {   // j = how far back in time
        int ls = l - j;
        if (ls >= 0) {
            float4 x = *(const float4*)(src + (size_t)ls * HIDN + c0);
            int k = 3 - j;
            y[0] += w[(c0 + 0) * 4 + k] * x.x;
            y[1] += w[(c0 + 1) * 4 + k] * x.y;
            y[2] += w[(c0 + 2) * 4 + k] * x.z;
            y[3] += w[(c0 + 3) * 4 + k] * x.w;
        }
    }
#pragma unroll
    for (int j = 0; j < 4; j++) y[j] = y[j] * sigmf(y[j]);
    const int head = c0 >> 6;
    const int d0 = c0 & 63;
    float* dst = g_proc + (size_t)z * NPROC + (((size_t)(b * HH + head)) * LL + l) * DD + d0;
    if (z < 2) {
        float ss = y[0] * y[0] + y[1] * y[1] + y[2] * y[2] + y[3] * y[3];
        atomicAdd(&hs[head], ss);
        __syncthreads();
        float scale = rsqrtf(hs[head] * (1.0f / 64.0f) + EPSF);
        const float* nw = (z == 0) ? qnw : knw;
#pragma unroll
        for (int j = 0; j < 4; j++) y[j] *= scale * nw[d0 + j];
    }
    float4 o; o.x = y[0]; o.y = y[1]; o.z = y[2]; o.w = y[3];
    *(float4*)dst = o;
}

// ---------------- K4: chunked recurrent scan, one block per (b,h) ----------------
// smem layout offsets (floats)
#define SW1_OFF 0
#define SW1_SZ  (64*132)
#define SW2_OFF (SW1_OFF+SW1_SZ)
#define SW2_SZ  (128*68)
#define SZ1_OFF (SW2_OFF+SW2_SZ)
#define SBUF_SZ (64*132)
#define SX1_OFF (SZ1_OFF+SBUF_SZ)
#define SSG_OFF (SX1_OFF+SBUF_SZ)
#define SKT_OFF (SSG_OFF+SBUF_SZ)
#define SKT_SZ  (64*68)
#define SGT_OFF (SKT_OFF+SKT_SZ)
#define SVC_OFF (SGT_OFF+SKT_SZ)
#define SVEC_OFF (SVC_OFF+SKT_SZ)
#define SMEM_FLOATS (SVEC_OFF + 577)
#define SMEM_BYTES (SMEM_FLOATS*4)

__global__ void __launch_bounds__(256, 1) k_scan(
    const float* __restrict__ W1g, const float* __restrict__ W2g, float* __restrict__ out)
{
    extern __shared__ float sm[];
    float* sW1 = sm + SW1_OFF;   // [64][132]  W1[d][c]
    float* sW2 = sm + SW2_OFF;   // [128][68]  W2[c][d]
    float* sZ1 = sm + SZ1_OFF;   // [64][132]  Z1 (later silu(Zq))
    float* sX1 = sm + SX1_OFF;   // [64][132]  X1 (later g_Z1)
    float* sSG = sm + SSG_OFF;   // [64][132]  sigmoid(Z1)
    float* sKT = sm + SKT_OFF;   // [64][68]   kc^T[d][i] (later qc^T)
    float* sGT = sm + SGT_OFF;   // [64][68]   g0^T[d][i] (later y^T[d][i])
    float* sVC = sm + SVC_OFF;   // [64][68]   vc[i][d]
    float* sW1s = sm + SVEC_OFF;          // 128
    float* sW2s = sW1s + 128;             // 64
    float* sKm  = sW2s + 64;              // 64
    float* sXm  = sKm + 64;               // 128
    float* sMd  = sXm + 128;              // 64
    float* sSd  = sMd + 64;               // 64
    float* sLr  = sSd + 64;               // 64
    float* sMp  = sLr + 64;               // 1

    const int t = threadIdx.x;
    const int bh = blockIdx.x;
    const int b = bh >> 4, h = bh & 15;
    const float* qp = g_proc + 0 * NPROC + (size_t)bh * LL * DD;
    const float* kp = g_proc + 1 * NPROC + (size_t)bh * LL * DD;
    const float* vp = g_proc + 2 * NPROC + (size_t)bh * LL * DD;
    const float* gmd = g_gate + 0 * NGATE + (size_t)bh * LL;
    const float* gsd = g_gate + 1 * NGATE + (size_t)bh * LL;
    const float* glr = g_gate + 2 * NGATE + (size_t)bh * LL;

    // init W1, W2, momenta
    for (int e = t; e < DD * DMM; e += 256) {
        int d = e >> 7, c = e & 127;
        sW1[d * 132 + c] = W1g[(size_t)h * DD * DMM + e];
    }
    for (int e = t; e < DMM * DD; e += 256) {
        int c = e >> 6, d = e & 63;
        sW2[c * 68 + d] = W2g[(size_t)h * DMM * DD + e];
    }
    if (t < 128) { sW1s[t] = 0.0f; sXm[t] = 0.0f; }
    if (t < 64)  { sW2s[t] = 0.0f; sKm[t] = 0.0f; }
    __syncthreads();

    const int ty4 = (t >> 4) * 4;
    const int tx8 = (t & 15) * 8;
    const int tx4 = (t & 15) * 4;

    for (int ch = 0; ch < NCH; ch++) {
        const int l0 = ch * CSZ;

        // --- A: load kc^T, vc, gates ---
        for (int e = t; e < CSZ * DD; e += 256) {
            int i = e >> 6, d = e & 63;
            sKT[d * 68 + i] = kp[(size_t)(l0 + i) * DD + d];
            sVC[i * 68 + d] = vp[(size_t)(l0 + i) * DD + d];
        }
        if (t < CSZ) { sMd[t] = gmd[l0 + t]; sSd[t] = gsd[l0 + t]; sLr[t] = glr[l0 + t]; }
        __syncthreads();

        // --- B: Z1 = kc @ W1 ; sig, X1 ---
        {
            float acc[4][8] = {};
            for (int k = 0; k < DD; k++) {
                float4 a = *(const float4*)&sKT[k * 68 + ty4];
                float4 b0 = *(const float4*)&sW1[k * 132 + tx8];
                float4 b1 = *(const float4*)&sW1[k * 132 + tx8 + 4];
                float ar[4] = {a.x, a.y, a.z, a.w};
                float br[8] = {b0.x, b0.y, b0.z, b0.w, b1.x, b1.y, b1.z, b1.w};
#pragma unroll
                for (int i = 0; i < 4; i++)
#pragma unroll
                    for (int j = 0; j < 8; j++) acc[i][j] += ar[i] * br[j];
            }
#pragma unroll
            for (int i = 0; i < 4; i++)
#pragma unroll
                for (int j = 0; j < 8; j++) {
                    float z = acc[i][j];
                    float sg = sigmf(z);
                    int idx = (ty4 + i) * 132 + tx8 + j;
                    sZ1[idx] = z; sSG[idx] = sg; sX1[idx] = z * sg;
                }
        }
        __syncthreads();

        // --- C: g0 = X1 @ W2 - vc  -> sGT[d][i] ---
        {
            float acc[4][4] = {};
            for (int k = 0; k < DMM; k++) {
                float a0 = sX1[(ty4 + 0) * 132 + k];
                float a1 = sX1[(ty4 + 1) * 132 + k];
                float a2 = sX1[(ty4 + 2) * 132 + k];
                float a3 = sX1[(ty4 + 3) * 132 + k];
                float4 bq = *(const float4*)&sW2[k * 68 + tx4];
                float br[4] = {bq.x, bq.y, bq.z, bq.w};
#pragma unroll
                for (int j = 0; j < 4; j++) {
                    acc[0][j] += a0 * br[j];
                    acc[1][j] += a1 * br[j];
                    acc[2][j] += a2 * br[j];
                    acc[3][j] += a3 * br[j];
                }
            }
#pragma unroll
            for (int i = 0; i < 4; i++)
#pragma unroll
                for (int j = 0; j < 4; j++)
                    sGT[(tx4 + j) * 68 + (ty4 + i)] = acc[i][j] - sVC[(ty4 + i) * 68 + tx4 + j];
        }
        __syncthreads();

        // --- D: momentum scans (xmom from X1, kmom from kc), mprod ---
        if (t < DMM) {
            float s = sXm[t];
#pragma unroll 8
            for (int tt = 0; tt < CSZ; tt++) s = sMd[tt] * s + sX1[tt * 132 + t];
            sXm[t] = s;
        } else if (t < DMM + DD) {
            int d = t - DMM;
            float s = sKm[d];
#pragma unroll 8
            for (int tt = 0; tt < CSZ; tt++) s = sMd[tt] * s + sKT[d * 68 + tt];
            sKm[d] = s;
        } else if (t == 255) {
            float p = 1.0f;
#pragma unroll 8
            for (int tt = 0; tt < CSZ; tt++) p *= sMd[tt];
            sMp[0] = p;
        }
        __syncthreads();

        // --- E: g_Z1 = -lr * (g0 @ W2^T) * silu_bwd(Z1) -> sX1 ---
        {
            float acc[4][8] = {};
            for (int k = 0; k < DD; k++) {
                float4 a = *(const float4*)&sGT[k * 68 + ty4];
                float ar[4] = {a.x, a.y, a.z, a.w};
                float br[8];
#pragma unroll
                for (int j = 0; j < 8; j++) br[j] = sW2[(tx8 + j) * 68 + k];
#pragma unroll
                for (int i = 0; i < 4; i++)
#pragma unroll
                    for (int j = 0; j < 8; j++) acc[i][j] += ar[i] * br[j];
            }
#pragma unroll
            for (int i = 0; i < 4; i++) {
                float nlr = -sLr[ty4 + i];
#pragma unroll
                for (int j = 0; j < 8; j++) {
                    int idx = (ty4 + i) * 132 + tx8 + j;
                    float z = sZ1[idx], sg = sSG[idx];
                    float sbw = sg * (1.0f + z * (1.0f - sg));
                    sX1[idx] = nlr * acc[i][j] * sbw;
                }
            }
        }
        __syncthreads();

        // --- F: surprise scans (W1s from g_Z1, W2s from -lr*g0) ---
        if (t < DMM) {
            float s = sW1s[t];
#pragma unroll 8
            for (int tt = 0; tt < CSZ; tt++) s = sSd[tt] * s + sX1[tt * 132 + t];
            sW1s[t] = s;
        } else if (t < DMM + DD) {
            int d = t - DMM;
            float s = sW2s[d];
#pragma unroll 8
            for (int tt = 0; tt < CSZ; tt++) s = sSd[tt] * s + (-sLr[tt]) * sGT[d * 68 + tt];
            sW2s[d] = s;
        }
        __syncthreads();

        // --- G: update W1, W2; load qc^T ---
        {
            float mp = sMp[0];
            for (int e = t; e < DD * DMM; e += 256) {
                int d = e >> 7, c = e & 127;
                sW1[d * 132 + c] = mp * sW1[d * 132 + c] + sKm[d] * sW1s[c];
            }
            for (int e = t; e < DMM * DD; e += 256) {
                int c = e >> 6, d = e & 63;
                sW2[c * 68 + d] = mp * sW2[c * 68 + d] + sXm[c] * sW2s[d];
            }
            for (int e = t; e < CSZ * DD; e += 256) {
                int i = e >> 6, d = e & 63;
                sKT[d * 68 + i] = qp[(size_t)(l0 + i) * DD + d];
            }
        }
        __syncthreads();

        // --- H: Zq = qc @ W1n ; silu -> sZ1 ---
        {
            float acc[4][8] = {};
            for (int k = 0; k < DD; k++) {
                float4 a = *(const float4*)&sKT[k * 68 + ty4];
                float4 b0 = *(const float4*)&sW1[k * 132 + tx8];
                float4 b1 = *(const float4*)&sW1[k * 132 + tx8 + 4];
                float ar[4] = {a.x, a.y, a.z, a.w};
                float br[8] = {b0.x, b0.y, b0.z, b0.w, b1.x, b1.y, b1.z, b1.w};
#pragma unroll
                for (int i = 0; i < 4; i++)
#pragma unroll
                    for (int j = 0; j < 8; j++) acc[i][j] += ar[i] * br[j];
            }
#pragma unroll
            for (int i = 0; i < 4; i++)
#pragma unroll
                for (int j = 0; j < 8; j++) {
                    float z = acc[i][j];
                    sZ1[(ty4 + i) * 132 + tx8 + j] = z * sigmf(z);
                }
        }
        __syncthreads();

        // --- I: y = silu(Zq) @ W2n -> sGT (transposed), then coalesced store ---
        {
            float acc[4][4] = {};
            for (int k = 0; k < DMM; k++) {
                float a0 = sZ1[(ty4 + 0) * 132 + k];
                float a1 = sZ1[(ty4 + 1) * 132 + k];
                float a2 = sZ1[(ty4 + 2) * 132 + k];
                float a3 = sZ1[(ty4 + 3) * 132 + k];
                float4 bq = *(const float4*)&sW2[k * 68 + tx4];
                float br[4] = {bq.x, bq.y, bq.z, bq.w};
#pragma unroll
                for (int j = 0; j < 4; j++) {
                    acc[0][j] += a0 * br[j];
                    acc[1][j] += a1 * br[j];
                    acc[2][j] += a2 * br[j];
                    acc[3][j] += a3 * br[j];
                }
            }
#pragma unroll
            for (int i = 0; i < 4; i++)
#pragma unroll
                for (int j = 0; j < 4; j++)
                    sGT[(tx4 + j) * 68 + (ty4 + i)] = acc[i][j];
        }
        __syncthreads();
        // output layout (per reference's raw reshape): out[b][(h*64+d)*L + l]
        for (int e = t; e < CSZ * DD; e += 256) {
            int d = e >> 6, i = e & 63;
            out[(size_t)b * LL * HIDN + ((size_t)(h * DD + d)) * LL + (l0 + i)] = sGT[d * 68 + i];
        }
        __syncthreads();
    }
}

// ---------------- launch ----------------
extern "C" void kernel_launch(void* const* d_in, const int* in_sizes, int n_in,
                              void* d_out, int out_size) {
    (void)in_sizes; (void)n_in; (void)out_size;
    const float* X    = (const float*)d_in[0];
    const float* Wq   = (const float*)d_in[1];
    const float* Wk   = (const float*)d_in[2];
    const float* Wv   = (const float*)d_in[3];
    const float* cqw  = (const float*)d_in[4];
    const float* cqb  = (const float*)d_in[5];
    const float* ckw  = (const float*)d_in[6];
    const float* ckb  = (const float*)d_in[7];
    const float* cvw  = (const float*)d_in[8];
    const float* cvb  = (const float*)d_in[9];
    const float* qnw  = (const float*)d_in[10];
    const float* knw  = (const float*)d_in[11];
    const float* mdw  = (const float*)d_in[12];
    const float* mdb  = (const float*)d_in[13];
    const float* sw   = (const float*)d_in[14];
    const float* sb   = (const float*)d_in[15];
    const float* lw   = (const float*)d_in[16];
    const float* lb   = (const float*)d_in[17];
    const float* W1g  = (const float*)d_in[18];
    const float* W2g  = (const float*)d_in[19];
    float* out = (float*)d_out;

    cudaFuncSetAttribute(k_scan, cudaFuncAttributeMaxDynamicSharedMemorySize, SMEM_BYTES);

    k_qkv<<<dim3(HIDN / 64, MM / 64, 3), 256>>>(X, Wq, Wk, Wv);
    k_gate<<<dim3(MM / 64), 256>>>(X, mdw, mdb, sw, sb, lw, lb);
    k_conv<<<dim3(LL, BB, 3), 256>>>(cqw, cqb, ckw, ckb, cvw, cvb, qnw, knw);
    k_scan<<<dim3(BB * HH), 256, SMEM_BYTES>>>(W1g, W2g, out);
}

// round 4
// speedup vs baseline: 1.8840x; 1.8840x over previous
#include <cuda_runtime.h>
#include <cuda_bf16.h>
#include <math.h>
#include <stdint.h>

#define BB 4
#define LL 4096
#define HIDN 1024
#define HH 16
#define DD 64
#define DMM 128
#define CSZ 64
#define NCH 64
#define MM (BB*LL)
#define EPSF 1e-6f
#define NPROC ((size_t)BB*HH*LL*DD)
#define NGATE ((size_t)BB*HH*LL)

static __device__ float g_qkv [(size_t)3*MM*HIDN];
static __device__ float g_proc[(size_t)3*NPROC];
static __device__ float g_gate[(size_t)3*NGATE];

__device__ __forceinline__ float sigmf(float x){ return __fdividef(1.0f, 1.0f + __expf(-x)); }

typedef unsigned long long ull;
#define FMA2(acc,a,b) asm("fma.rn.f32x2 %0,%1,%2,%0;" : "+l"(acc) : "l"(a), "l"(b))
__device__ __forceinline__ ull dup2(float a){ ull r; asm("mov.b64 %0,{%1,%1};" : "=l"(r) : "r"(__float_as_uint(a))); return r; }
__device__ __forceinline__ float2 unp(ull v){ uint32_t l,h; asm("mov.b64 {%0,%1},%2;" : "=r"(l),"=r"(h) : "l"(v)); return make_float2(__uint_as_float(l),__uint_as_float(h)); }
__device__ __forceinline__ uint32_t smem_u32(const void* p){
    uint32_t a; asm("{ .reg .u64 t; cvta.to.shared.u64 t, %1; cvt.u32.u64 %0, t; }" : "=r"(a) : "l"(p)); return a;
}
__device__ __forceinline__ void ldsm4(uint32_t* r, uint32_t a){
    asm volatile("ldmatrix.sync.aligned.m8n8.x4.shared.b16 {%0,%1,%2,%3},[%4];"
        : "=r"(r[0]),"=r"(r[1]),"=r"(r[2]),"=r"(r[3]) : "r"(a));
}
__device__ __forceinline__ void ldsm2(uint32_t* r, uint32_t a){
    asm volatile("ldmatrix.sync.aligned.m8n8.x2.shared.b16 {%0,%1},[%2];"
        : "=r"(r[0]),"=r"(r[1]) : "r"(a));
}
__device__ __forceinline__ void mma16816(float* c, const uint32_t* a, const uint32_t* b){
    asm volatile("mma.sync.aligned.m16n8k16.row.col.f32.bf16.bf16.f32 "
        "{%0,%1,%2,%3},{%4,%5,%6,%7},{%8,%9},{%0,%1,%2,%3};"
        : "+f"(c[0]),"+f"(c[1]),"+f"(c[2]),"+f"(c[3])
        : "r"(a[0]),"r"(a[1]),"r"(a[2]),"r"(a[3]),"r"(b[0]),"r"(b[1]));
}
__device__ __forceinline__ void pack8(float4 u, float4 v, uint4& hi, uint4& lo){
    float f[8] = {u.x,u.y,u.z,u.w,v.x,v.y,v.z,v.w};
    uint32_t hw[8], lw[8];
#pragma unroll
    for (int j = 0; j < 8; j++){
        __nv_bfloat16 h = __float2bfloat16_rn(f[j]);
        __nv_bfloat16 l = __float2bfloat16_rn(f[j] - __bfloat162float(h));
        hw[j] = (uint32_t)*(unsigned short*)&h;
        lw[j] = (uint32_t)*(unsigned short*)&l;
    }
    hi.x = hw[0]|(hw[1]<<16); hi.y = hw[2]|(hw[3]<<16); hi.z = hw[4]|(hw[5]<<16); hi.w = hw[6]|(hw[7]<<16);
    lo.x = lw[0]|(lw[1]<<16); lo.y = lw[2]|(lw[3]<<16); lo.z = lw[4]|(lw[5]<<16); lo.w = lw[6]|(lw[7]<<16);
}

// ---------------- K1: qkv GEMM via mma.sync bf16 3-term split ----------------
// stage layout (bytes): Ahi[128][24bf16] @0, Alo @6144, Bhi @12288, Blo @18432; stage size 24576
#define STG_B 24576
#define QSMEM (2*STG_B)

__global__ void __launch_bounds__(256) k_qkv(
    const float* __restrict__ X,
    const float* __restrict__ Wq, const float* __restrict__ Wk, const float* __restrict__ Wv)
{
    extern __shared__ __align__(16) char qs[];
    const int t = threadIdx.x, wid = t>>5, lam = t&31;
    const int z = blockIdx.z, n0 = blockIdx.x*128, m0 = blockIdx.y*128;
    const float* W = (z==0)?Wq:(z==1)?Wk:Wv;
    const uint32_t sb = smem_u32(qs);
    const int r = t>>1, q = t&1;
    const float* xrow = X + (size_t)(m0+r)*HIDN + q*8;
    const float* wrow = W + (size_t)(n0+r)*HIDN + q*8;
    const int soff = r*48 + q*16;

    float acc[4][4][4] = {};
    const int wm = (wid>>2)*64, wn = (wid&3)*32;
    const uint32_t a_l = (uint32_t)((lam & 15)*48 + (lam>>4)*16);
    const uint32_t b_l = (uint32_t)((lam & 7)*48 + ((lam>>3)&1)*16);

    {   // preload stage 0 (k0 = 0)
        float4 u = *(const float4*)(xrow), v = *(const float4*)(xrow + 4);
        uint4 hi, lo; pack8(u, v, hi, lo);
        *(uint4*)(qs + soff) = hi; *(uint4*)(qs + 6144 + soff) = lo;
        u = *(const float4*)(wrow); v = *(const float4*)(wrow + 4);
        pack8(u, v, hi, lo);
        *(uint4*)(qs + 12288 + soff) = hi; *(uint4*)(qs + 18432 + soff) = lo;
    }
    __syncthreads();

    for (int s = 0; s < 64; s++){
        if (s < 63){
            char* nxt = qs + ((s+1)&1)*STG_B;
            int k0 = (s+1)*16;
            float4 u = *(const float4*)(xrow + k0), v = *(const float4*)(xrow + k0 + 4);
            uint4 hi, lo; pack8(u, v, hi, lo);
            *(uint4*)(nxt + soff) = hi; *(uint4*)(nxt + 6144 + soff) = lo;
            u = *(const float4*)(wrow + k0); v = *(const float4*)(wrow + k0 + 4);
            pack8(u, v, hi, lo);
            *(uint4*)(nxt + 12288 + soff) = hi; *(uint4*)(nxt + 18432 + soff) = lo;
        }
        uint32_t cb = sb + (s&1)*STG_B;
        uint32_t ah[4][4], al[4][4], bh[4][2], bl[4][2];
#pragma unroll
        for (int mi = 0; mi < 4; mi++){
            uint32_t rowb = cb + (uint32_t)(wm + mi*16)*48 + a_l;
            ldsm4(ah[mi], rowb);
            ldsm4(al[mi], rowb + 6144);
        }
#pragma unroll
        for (int ni = 0; ni < 4; ni++){
            uint32_t rowb = cb + 12288 + (uint32_t)(wn + ni*8)*48 + b_l;
            ldsm2(bh[ni], rowb);
            ldsm2(bl[ni], rowb + 6144);
        }
#pragma unroll
        for (int mi = 0; mi < 4; mi++)
#pragma unroll
            for (int ni = 0; ni < 4; ni++){
                mma16816(acc[mi][ni], ah[mi], bh[ni]);
                mma16816(acc[mi][ni], ah[mi], bl[ni]);
                mma16816(acc[mi][ni], al[mi], bh[ni]);
            }
        __syncthreads();
    }

    float* C = g_qkv + (size_t)z*MM*HIDN;
    const int rr = lam>>2, cc2 = (lam&3)*2;
#pragma unroll
    for (int mi = 0; mi < 4; mi++){
        int row0 = m0 + wm + mi*16 + rr;
#pragma unroll
        for (int ni = 0; ni < 4; ni++){
            int col = n0 + wn + ni*8 + cc2;
            *(float2*)&C[(size_t)row0*HIDN + col]     = make_float2(acc[mi][ni][0], acc[mi][ni][1]);
            *(float2*)&C[(size_t)(row0+8)*HIDN + col] = make_float2(acc[mi][ni][2], acc[mi][ni][3]);
        }
    }
}

// ---------------- K2: gate projections ----------------
__global__ void __launch_bounds__(256) k_gate(
    const float* __restrict__ X,
    const float* __restrict__ mdw, const float* __restrict__ mdb,
    const float* __restrict__ sw,  const float* __restrict__ sb,
    const float* __restrict__ lw,  const float* __restrict__ lb)
{
    __shared__ float As[16][68];
    __shared__ float Bg[16][52];
    const int m0 = blockIdx.x * 64;
    const int t = threadIdx.x;
    const int lr = t >> 2, lk = (t & 3) * 4;
    const int ty = t >> 4, tx = t & 15;
    float acc[4][3] = {};
    const float* Arow = X + (size_t)(m0 + lr) * HIDN + lk;
    for (int k0 = 0; k0 < HIDN; k0 += 16){
        float4 av = *(const float4*)(Arow + k0);
        As[lk+0][lr]=av.x; As[lk+1][lr]=av.y; As[lk+2][lr]=av.z; As[lk+3][lr]=av.w;
        if (t < 192){
#pragma unroll
            for (int j = 0; j < 4; j++){
                int idx = t*4+j, n = idx>>4, k = idx&15;
                const float* wp = (n<16)?(mdw+(size_t)n*HIDN):(n<32)?(sw+(size_t)(n-16)*HIDN):(lw+(size_t)(n-32)*HIDN);
                Bg[k][n] = wp[k0+k];
            }
        }
        __syncthreads();
#pragma unroll
        for (int kk = 0; kk < 16; kk++){
            float4 a = *(const float4*)&As[kk][ty*4];
            float ar[4] = {a.x,a.y,a.z,a.w};
            float b0=Bg[kk][tx*3], b1=Bg[kk][tx*3+1], b2=Bg[kk][tx*3+2];
#pragma unroll
            for (int i = 0; i < 4; i++){ acc[i][0]+=ar[i]*b0; acc[i][1]+=ar[i]*b1; acc[i][2]+=ar[i]*b2; }
        }
        __syncthreads();
    }
#pragma unroll
    for (int i = 0; i < 4; i++)
#pragma unroll
        for (int j = 0; j < 3; j++){
            int m = m0 + ty*4 + i, o = tx*3 + j;
            float bias = (o<16)?mdb[o]:(o<32)?sb[o-16]:lb[o-32];
            float v = sigmf(acc[i][j] + bias);
            int bc = m >> 12, l = m & (LL-1), g = o >> 4, hh = o & 15;
            g_gate[(size_t)g*NGATE + ((size_t)(bc*HH+hh))*LL + l] = (g==0)?(1.0f-v):v;
        }
}

// ---------------- K3: causal conv + silu (+rmsnorm) ----------------
__global__ void __launch_bounds__(256) k_conv(
    const float* __restrict__ cqw, const float* __restrict__ cqb,
    const float* __restrict__ ckw, const float* __restrict__ ckb,
    const float* __restrict__ cvw, const float* __restrict__ cvb,
    const float* __restrict__ qnw, const float* __restrict__ knw)
{
    const int z = blockIdx.z, b = blockIdx.y, l = blockIdx.x;
    const float* w    = (z==0)?cqw:(z==1)?ckw:cvw;
    const float* bias = (z==0)?cqb:(z==1)?ckb:cvb;
    const float* src = g_qkv + (size_t)z*MM*HIDN + (size_t)b*LL*HIDN;
    __shared__ float hs[16];
    const int t = threadIdx.x;
    if (t < 16) hs[t] = 0.0f;
    __syncthreads();
    const int c0 = t*4;
    float y[4];
#pragma unroll
    for (int j = 0; j < 4; j++) y[j] = bias[c0+j];
#pragma unroll
    for (int j = 0; j < 4; j++){
        int ls = l - j;
        if (ls >= 0){
            float4 x = *(const float4*)(src + (size_t)ls*HIDN + c0);
            int k = 3 - j;
            y[0]+=w[(c0+0)*4+k]*x.x; y[1]+=w[(c0+1)*4+k]*x.y; y[2]+=w[(c0+2)*4+k]*x.z; y[3]+=w[(c0+3)*4+k]*x.w;
        }
    }
#pragma unroll
    for (int j = 0; j < 4; j++) y[j] = y[j]*sigmf(y[j]);
    const int head = c0 >> 6, d0 = c0 & 63;
    float* dst = g_proc + (size_t)z*NPROC + (((size_t)(b*HH+head))*LL + l)*DD + d0;
    if (z < 2){
        atomicAdd(&hs[head], y[0]*y[0]+y[1]*y[1]+y[2]*y[2]+y[3]*y[3]);
        __syncthreads();
        float sc = rsqrtf(hs[head]*(1.0f/64.0f) + EPSF);
        const float* nw = (z==0)?qnw:knw;
#pragma unroll
        for (int j = 0; j < 4; j++) y[j] *= sc*nw[d0+j];
    }
    float4 o; o.x=y[0]; o.y=y[1]; o.z=y[2]; o.w=y[3];
    *(float4*)dst = o;
}

// ---------------- K4: chunked scan, 512 threads, f32x2 ----------------
#define OW1 0
#define OW2 8448
#define OW2T 17152
#define OZ1 25600
#define OX1 34048
#define OKC 42496
#define OKT 46848
#define OGT 51200
#define OVV 55552
#define SCAN_BYTES ((OVV + 577)*4)

__global__ void __launch_bounds__(512,1) k_scan(
    const float* __restrict__ W1g, const float* __restrict__ W2g, float* __restrict__ out)
{
    extern __shared__ float sm[];
    float* sW1  = sm + OW1;   // [64][132] W1[d][c]
    float* sW2  = sm + OW2;   // [128][68] W2[c][d]
    float* sW2T = sm + OW2T;  // [64][132] W2T[d][c]
    float* sZ1  = sm + OZ1;   // [64][132] (i,c)
    float* sX1  = sm + OX1;   // [64][132] (i,c)
    float* sKC  = sm + OKC;   // [64][68] kc (i,d)
    float* sKT  = sm + OKT;   // [64][68] kc^T / qc^T (d,i)
    float* sGT  = sm + OGT;   // [64][68] g0^T / y^T (d,i)
    float* sW1s = sm + OVV; float* sW2s = sW1s+128; float* sKm = sW2s+64;
    float* sXm  = sKm+64;   float* sMd  = sXm+128;  float* sSd = sMd+64;
    float* sLr  = sSd+64;   float* sMp  = sLr+64;

    const int t = threadIdx.x;
    const int bh = blockIdx.x, b = bh >> 4, h = bh & 15;
    const float* qp = g_proc + 0*NPROC + (size_t)bh*LL*DD;
    const float* kp = g_proc + 1*NPROC + (size_t)bh*LL*DD;
    const float* vp = g_proc + 2*NPROC + (size_t)bh*LL*DD;
    const float* gmd = g_gate + 0*NGATE + (size_t)bh*LL;
    const float* gsd = g_gate + 1*NGATE + (size_t)bh*LL;
    const float* glr = g_gate + 2*NGATE + (size_t)bh*LL;

    for (int e = t; e < DD*DMM; e += 512){ int d=e>>7, c=e&127; sW1[d*132+c] = W1g[(size_t)h*DD*DMM+e]; }
    for (int e = t; e < DMM*DD; e += 512){ int c=e>>6, d=e&63; float v=W2g[(size_t)h*DMM*DD+e]; sW2[c*68+d]=v; sW2T[d*132+c]=v; }
    if (t < 128){ sW1s[t]=0.0f; sXm[t]=0.0f; }
    if (t < 64){ sW2s[t]=0.0f; sKm[t]=0.0f; }
    __syncthreads();

    const int r0 = (t>>5)*4;
    const int c0 = (t&31)*4;
    const int c2 = (t&31)*2;

    for (int ch = 0; ch < NCH; ch++){
        const int l0 = ch*CSZ;
        float vcr[4][2];
        for (int e = t; e < CSZ*DD; e += 512){
            int i = e>>6, d = e&63;
            float kv = kp[(size_t)(l0+i)*DD + d];
            sKC[i*68+d] = kv; sKT[d*68+i] = kv;
        }
#pragma unroll
        for (int i = 0; i < 4; i++){
            float2 vv = *(const float2*)(vp + (size_t)(l0+r0+i)*DD + c2);
            vcr[i][0]=vv.x; vcr[i][1]=vv.y;
        }
        if (t < CSZ){ sMd[t]=gmd[l0+t]; sSd[t]=gsd[l0+t]; sLr[t]=glr[l0+t]; }
        __syncthreads();

        // B: Z1 = kc@W1, X1 = silu(Z1)
        {
            ull acc[4][2] = {};
            for (int d = 0; d < DD; d++){
                float4 a = *(const float4*)&sKT[d*68+r0];
                ull a0=dup2(a.x),a1=dup2(a.y),a2=dup2(a.z),a3=dup2(a.w);
                ulonglong2 bv = *(const ulonglong2*)&sW1[d*132+c0];
                FMA2(acc[0][0],a0,bv.x); FMA2(acc[0][1],a0,bv.y);
                FMA2(acc[1][0],a1,bv.x); FMA2(acc[1][1],a1,bv.y);
                FMA2(acc[2][0],a2,bv.x); FMA2(acc[2][1],a2,bv.y);
                FMA2(acc[3][0],a3,bv.x); FMA2(acc[3][1],a3,bv.y);
            }
#pragma unroll
            for (int i = 0; i < 4; i++){
                float2 p = unp(acc[i][0]), q = unp(acc[i][1]);
                *(float4*)&sZ1[(r0+i)*132+c0] = make_float4(p.x,p.y,q.x,q.y);
                *(float4*)&sX1[(r0+i)*132+c0] =
                    make_float4(p.x*sigmf(p.x), p.y*sigmf(p.y), q.x*sigmf(q.x), q.y*sigmf(q.y));
            }
        }
        __syncthreads();

        // C: g0 = X1@W2 - vc -> sGT (transposed)
        {
            ull acc[4] = {};
            for (int cc = 0; cc < DMM; cc += 4){
                float4 a0 = *(const float4*)&sX1[(r0+0)*132+cc];
                float4 a1 = *(const float4*)&sX1[(r0+1)*132+cc];
                float4 a2 = *(const float4*)&sX1[(r0+2)*132+cc];
                float4 a3 = *(const float4*)&sX1[(r0+3)*132+cc];
#pragma unroll
                for (int u = 0; u < 4; u++){
                    ull bv = *(const ull*)&sW2[(cc+u)*68+c2];
                    float e0 = u==0?a0.x:u==1?a0.y:u==2?a0.z:a0.w;
                    float e1 = u==0?a1.x:u==1?a1.y:u==2?a1.z:a1.w;
                    float e2 = u==0?a2.x:u==1?a2.y:u==2?a2.z:a2.w;
                    float e3 = u==0?a3.x:u==1?a3.y:u==2?a3.z:a3.w;
                    FMA2(acc[0],dup2(e0),bv); FMA2(acc[1],dup2(e1),bv);
                    FMA2(acc[2],dup2(e2),bv); FMA2(acc[3],dup2(e3),bv);
                }
            }
#pragma unroll
            for (int i = 0; i < 4; i++){
                float2 p = unp(acc[i]);
                sGT[(c2+0)*68+(r0+i)] = p.x - vcr[i][0];
                sGT[(c2+1)*68+(r0+i)] = p.y - vcr[i][1];
            }
        }
        __syncthreads();

        // D: momentum scans + mprod
        if (t < DMM){
            float s = sXm[t];
#pragma unroll 8
            for (int tt = 0; tt < CSZ; tt++) s = sMd[tt]*s + sX1[tt*132+t];
            sXm[t] = s;
        } else if (t < DMM+DD){
            int d = t - DMM; float s = sKm[d];
#pragma unroll 8
            for (int tt = 0; tt < CSZ; tt++) s = sMd[tt]*s + sKC[tt*68+d];
            sKm[d] = s;
        } else if (t == 504){
            float p = 1.0f;
#pragma unroll 8
            for (int tt = 0; tt < CSZ; tt++) p *= sMd[tt];
            sMp[0] = p;
        }
        __syncthreads();

        // E: g_Z1 = -lr*(g0@W2^T)*silu_bwd(Z1) -> sX1
        {
            ull acc[4][2] = {};
            for (int d = 0; d < DD; d++){
                float4 a = *(const float4*)&sGT[d*68+r0];
                ull a0=dup2(a.x),a1=dup2(a.y),a2=dup2(a.z),a3=dup2(a.w);
                ulonglong2 bv = *(const ulonglong2*)&sW2T[d*132+c0];
                FMA2(acc[0][0],a0,bv.x); FMA2(acc[0][1],a0,bv.y);
                FMA2(acc[1][0],a1,bv.x); FMA2(acc[1][1],a1,bv.y);
                FMA2(acc[2][0],a2,bv.x); FMA2(acc[2][1],a2,bv.y);
                FMA2(acc[3][0],a3,bv.x); FMA2(acc[3][1],a3,bv.y);
            }
#pragma unroll
            for (int i = 0; i < 4; i++){
                float nlr = -sLr[r0+i];
                float2 p = unp(acc[i][0]), q = unp(acc[i][1]);
                float g[4] = {p.x,p.y,q.x,q.y};
                float4 o;
#pragma unroll
                for (int j = 0; j < 4; j++){
                    float z = sZ1[(r0+i)*132+c0+j];
                    float sg = sigmf(z);
                    ((float*)&o)[j] = nlr*g[j]*(sg*(1.0f + z*(1.0f - sg)));
                }
                *(float4*)&sX1[(r0+i)*132+c0] = o;
            }
        }
        __syncthreads();

        // F: surprise scans
        if (t < DMM){
            float s = sW1s[t];
#pragma unroll 8
            for (int tt = 0; tt < CSZ; tt++) s = sSd[tt]*s + sX1[tt*132+t];
            sW1s[t] = s;
        } else if (t < DMM+DD){
            int d = t - DMM; float s = sW2s[d];
#pragma unroll 8
            for (int tt = 0; tt < CSZ; tt++) s = sSd[tt]*s + (-sLr[tt])*sGT[d*68+tt];
            sW2s[d] = s;
        }
        __syncthreads();

        // G: update W1/W2/W2T; load qc^T
        {
            float mp = sMp[0];
            for (int e = t; e < DD*DMM; e += 512){
                int d = e>>7, c = e&127;
                sW1[d*132+c] = mp*sW1[d*132+c] + sKm[d]*sW1s[c];
            }
            for (int e = t; e < DMM*DD; e += 512){
                int c = e>>6, d = e&63;
                float v = mp*sW2[c*68+d] + sXm[c]*sW2s[d];
                sW2[c*68+d] = v; sW2T[d*132+c] = v;
            }
            for (int e = t; e < CSZ*DD; e += 512){
                int i = e>>6, d = e&63;
                sKT[d*68+i] = qp[(size_t)(l0+i)*DD + d];
            }
        }
        __syncthreads();

        // H: Zq = qc@W1n ; silu -> sZ1
        {
            ull acc[4][2] = {};
            for (int d = 0; d < DD; d++){
                float4 a = *(const float4*)&sKT[d*68+r0];
                ull a0=dup2(a.x),a1=dup2(a.y),a2=dup2(a.z),a3=dup2(a.w);
                ulonglong2 bv = *(const ulonglong2*)&sW1[d*132+c0];
                FMA2(acc[0][0],a0,bv.x); FMA2(acc[0][1],a0,bv.y);
                FMA2(acc[1][0],a1,bv.x); FMA2(acc[1][1],a1,bv.y);
                FMA2(acc[2][0],a2,bv.x); FMA2(acc[2][1],a2,bv.y);
                FMA2(acc[3][0],a3,bv.x); FMA2(acc[3][1],a3,bv.y);
            }
#pragma unroll
            for (int i = 0; i < 4; i++){
                float2 p = unp(acc[i][0]), q = unp(acc[i][1]);
                *(float4*)&sZ1[(r0+i)*132+c0] =
                    make_float4(p.x*sigmf(p.x), p.y*sigmf(p.y), q.x*sigmf(q.x), q.y*sigmf(q.y));
            }
        }
        __syncthreads();

        // I: y = silu(Zq)@W2n -> sGT (transposed)
        {
            ull acc[4] = {};
            for (int cc = 0; cc < DMM; cc += 4){
                float4 a0 = *(const float4*)&sZ1[(r0+0)*132+cc];
                float4 a1 = *(const float4*)&sZ1[(r0+1)*132+cc];
                float4 a2 = *(const float4*)&sZ1[(r0+2)*132+cc];
                float4 a3 = *(const float4*)&sZ1[(r0+3)*132+cc];
#pragma unroll
                for (int u = 0; u < 4; u++){
                    ull bv = *(const ull*)&sW2[(cc+u)*68+c2];
                    float e0 = u==0?a0.x:u==1?a0.y:u==2?a0.z:a0.w;
                    float e1 = u==0?a1.x:u==1?a1.y:u==2?a1.z:a1.w;
                    float e2 = u==0?a2.x:u==1?a2.y:u==2?a2.z:a2.w;
                    float e3 = u==0?a3.x:u==1?a3.y:u==2?a3.z:a3.w;
                    FMA2(acc[0],dup2(e0),bv); FMA2(acc[1],dup2(e1),bv);
                    FMA2(acc[2],dup2(e2),bv); FMA2(acc[3],dup2(e3),bv);
                }
            }
#pragma unroll
            for (int i = 0; i < 4; i++){
                float2 p = unp(acc[i]);
                sGT[(c2+0)*68+(r0+i)] = p.x;
                sGT[(c2+1)*68+(r0+i)] = p.y;
            }
        }
        __syncthreads();
        for (int e = t; e < CSZ*DD; e += 512){
            int d = e>>6, i = e&63;
            out[(size_t)b*LL*HIDN + ((size_t)(h*DD+d))*LL + (l0+i)] = sGT[d*68+i];
        }
        __syncthreads();
    }
}

// ---------------- launch ----------------
extern "C" void kernel_launch(void* const* d_in, const int* in_sizes, int n_in,
                              void* d_out, int out_size) {
    (void)in_sizes; (void)n_in; (void)out_size;
    const float* X   = (const float*)d_in[0];
    const float* Wq  = (const float*)d_in[1];
    const float* Wk  = (const float*)d_in[2];
    const float* Wv  = (const float*)d_in[3];
    const float* cqw = (const float*)d_in[4];
    const float* cqb = (const float*)d_in[5];
    const float* ckw = (const float*)d_in[6];
    const float* ckb = (const float*)d_in[7];
    const float* cvw = (const float*)d_in[8];
    const float* cvb = (const float*)d_in[9];
    const float* qnw = (const float*)d_in[10];
    const float* knw = (const float*)d_in[11];
    const float* mdw = (const float*)d_in[12];
    const float* mdb = (const float*)d_in[13];
    const float* sw  = (const float*)d_in[14];
    const float* sb  = (const float*)d_in[15];
    const float* lw  = (const float*)d_in[16];
    const float* lb  = (const float*)d_in[17];
    const float* W1g = (const float*)d_in[18];
    const float* W2g = (const float*)d_in[19];
    float* out = (float*)d_out;

    cudaFuncSetAttribute(k_qkv, cudaFuncAttributeMaxDynamicSharedMemorySize, QSMEM);
    cudaFuncSetAttribute(k_scan, cudaFuncAttributeMaxDynamicSharedMemorySize, SCAN_BYTES);

    k_qkv<<<dim3(HIDN/128, MM/128, 3), 256, QSMEM>>>(X, Wq, Wk, Wv);
    k_gate<<<dim3(MM/64), 256>>>(X, mdw, mdb, sw, sb, lw, lb);
    k_conv<<<dim3(LL, BB, 3), 256>>>(cqw, cqb, ckw, ckb, cvw, cvb, qnw, knw);
    k_scan<<<dim3(BB*HH), 512, SCAN_BYTES>>>(W1g, W2g, out);
}

// round 5
// speedup vs baseline: 2.1060x; 1.1179x over previous
#include <cuda_runtime.h>
#include <cuda_bf16.h>
#include <math.h>
#include <stdint.h>

#define BB 4
#define LL 4096
#define HIDN 1024
#define HH 16
#define DD 64
#define DMM 128
#define CSZ 64
#define NCH 64
#define MM (BB*LL)
#define EPSF 1e-6f
#define NPROC ((size_t)BB*HH*LL*DD)
#define NGATE ((size_t)BB*HH*LL)

static __device__ float g_qkv [(size_t)3*MM*HIDN];
static __device__ float g_proc[(size_t)3*NPROC];
static __device__ float g_gate[(size_t)3*NGATE];
static __device__ __nv_bfloat16 g_Xhi[(size_t)MM*HIDN];
static __device__ __nv_bfloat16 g_Xlo[(size_t)MM*HIDN];
static __device__ __nv_bfloat16 g_Whi[(size_t)3*HIDN*HIDN];
static __device__ __nv_bfloat16 g_Wlo[(size_t)3*HIDN*HIDN];

__device__ __forceinline__ float sigmf(float x){ return __fdividef(1.0f, 1.0f + __expf(-x)); }

typedef unsigned long long ull;
#define FMA2(acc,a,b) asm("fma.rn.f32x2 %0,%1,%2,%0;" : "+l"(acc) : "l"(a), "l"(b))
__device__ __forceinline__ ull dup2(float a){ ull r; asm("mov.b64 %0,{%1,%1};" : "=l"(r) : "r"(__float_as_uint(a))); return r; }
__device__ __forceinline__ float2 unp(ull v){ uint32_t l,h; asm("mov.b64 {%0,%1},%2;" : "=r"(l),"=r"(h) : "l"(v)); return make_float2(__uint_as_float(l),__uint_as_float(h)); }
__device__ __forceinline__ uint32_t smem_u32(const void* p){
    uint32_t a; asm("{ .reg .u64 t; cvta.to.shared.u64 t, %1; cvt.u32.u64 %0, t; }" : "=r"(a) : "l"(p)); return a;
}
__device__ __forceinline__ void ldsm4(uint32_t* r, uint32_t a){
    asm volatile("ldmatrix.sync.aligned.m8n8.x4.shared.b16 {%0,%1,%2,%3},[%4];"
        : "=r"(r[0]),"=r"(r[1]),"=r"(r[2]),"=r"(r[3]) : "r"(a));
}
__device__ __forceinline__ void ldsm2(uint32_t* r, uint32_t a){
    asm volatile("ldmatrix.sync.aligned.m8n8.x2.shared.b16 {%0,%1},[%2];"
        : "=r"(r[0]),"=r"(r[1]) : "r"(a));
}
__device__ __forceinline__ void mma16816(float* c, const uint32_t* a, const uint32_t* b){
    asm volatile("mma.sync.aligned.m16n8k16.row.col.f32.bf16.bf16.f32 "
        "{%0,%1,%2,%3},{%4,%5,%6,%7},{%8,%9},{%0,%1,%2,%3};"
        : "+f"(c[0]),"+f"(c[1]),"+f"(c[2]),"+f"(c[3])
        : "r"(a[0]),"r"(a[1]),"r"(a[2]),"r"(a[3]),"r"(b[0]),"r"(b[1]));
}
#define CPA(dst,src) asm volatile("cp.async.cg.shared.global [%0],[%1],16;" :: "r"(dst),"l"(src))
#define CPC() asm volatile("cp.async.commit_group;" ::: "memory")
#define CPW(n) asm volatile("cp.async.wait_group %0;" :: "n"(n) : "memory")

// ---------------- K0: fp32 -> bf16 hi/lo ----------------
__global__ void __launch_bounds__(256) k_split(const float* __restrict__ src,
    __nv_bfloat16* __restrict__ hi, __nv_bfloat16* __restrict__ lo, int n)
{
    int i = (blockIdx.x*256 + threadIdx.x)*4;
    if (i >= n) return;
    float4 v = *(const float4*)(src + i);
    float f[4] = {v.x,v.y,v.z,v.w};
    __nv_bfloat16 h[4], l[4];
#pragma unroll
    for (int j = 0; j < 4; j++){
        h[j] = __float2bfloat16_rn(f[j]);
        l[j] = __float2bfloat16_rn(f[j] - __bfloat162float(h[j]));
    }
    *(__nv_bfloat162*)(hi+i)   = __halves2bfloat162(h[0],h[1]);
    *(__nv_bfloat162*)(hi+i+2) = __halves2bfloat162(h[2],h[3]);
    *(__nv_bfloat162*)(lo+i)   = __halves2bfloat162(l[0],l[1]);
    *(__nv_bfloat162*)(lo+i+2) = __halves2bfloat162(l[2],l[3]);
}

// ---------------- K1: qkv GEMM, mma.sync bf16 3-term, cp.async 4-stage ----------------
#define STG_B 24576
#define QSMEM (4*STG_B)

__global__ void __launch_bounds__(256) k_qkv()
{
    extern __shared__ __align__(16) char qs[];
    const int t = threadIdx.x, wid = t>>5, lam = t&31;
    const int z = blockIdx.z, n0 = blockIdx.x*128, m0 = blockIdx.y*128;
    const uint32_t sb = smem_u32(qs);
    const int r = t>>1, q = t&1;
    const __nv_bfloat16* Ah = g_Xhi + (size_t)(m0+r)*HIDN + q*8;
    const __nv_bfloat16* Al = g_Xlo + (size_t)(m0+r)*HIDN + q*8;
    const __nv_bfloat16* Bh = g_Whi + (size_t)z*HIDN*HIDN + (size_t)(n0+r)*HIDN + q*8;
    const __nv_bfloat16* Bl = g_Wlo + (size_t)z*HIDN*HIDN + (size_t)(n0+r)*HIDN + q*8;
    const uint32_t soff = (uint32_t)(r*48 + q*16);

    float acc[4][4][4] = {};
    const int wm = (wid>>2)*64, wn = (wid&3)*32;
    const uint32_t a_l = (uint32_t)((lam & 15)*48 + (lam>>4)*16);
    const uint32_t b_l = (uint32_t)((lam & 7)*48 + ((lam>>3)&1)*16);

#define ISSUE(s_) do{ uint32_t ds = sb + (uint32_t)(((s_)&3)*STG_B) + soff; int k0 = (s_)*16; \
    CPA(ds,       Ah + k0); CPA(ds+6144,  Al + k0); \
    CPA(ds+12288, Bh + k0); CPA(ds+18432, Bl + k0); CPC(); }while(0)

    ISSUE(0); ISSUE(1); ISSUE(2);
    for (int s = 0; s < 64; s++){
        CPW(2);
        __syncthreads();
        if (s < 61) ISSUE(s+3); else CPC();
        uint32_t cb = sb + (uint32_t)((s&3)*STG_B);
        uint32_t ah[4][4], al[4][4], bh[4][2], bl[4][2];
#pragma unroll
        for (int mi = 0; mi < 4; mi++){
            uint32_t rowb = cb + (uint32_t)(wm + mi*16)*48 + a_l;
            ldsm4(ah[mi], rowb); ldsm4(al[mi], rowb + 6144);
        }
#pragma unroll
        for (int ni = 0; ni < 4; ni++){
            uint32_t rowb = cb + 12288 + (uint32_t)(wn + ni*8)*48 + b_l;
            ldsm2(bh[ni], rowb); ldsm2(bl[ni], rowb + 6144);
        }
#pragma unroll
        for (int mi = 0; mi < 4; mi++)
#pragma unroll
            for (int ni = 0; ni < 4; ni++){
                mma16816(acc[mi][ni], ah[mi], bh[ni]);
                mma16816(acc[mi][ni], ah[mi], bl[ni]);
                mma16816(acc[mi][ni], al[mi], bh[ni]);
            }
    }
#undef ISSUE
    float* C = g_qkv + (size_t)z*MM*HIDN;
    const int rr = lam>>2, cc2 = (lam&3)*2;
#pragma unroll
    for (int mi = 0; mi < 4; mi++){
        int row0 = m0 + wm + mi*16 + rr;
#pragma unroll
        for (int ni = 0; ni < 4; ni++){
            int col = n0 + wn + ni*8 + cc2;
            *(float2*)&C[(size_t)row0*HIDN + col]     = make_float2(acc[mi][ni][0], acc[mi][ni][1]);
            *(float2*)&C[(size_t)(row0+8)*HIDN + col] = make_float2(acc[mi][ni][2], acc[mi][ni][3]);
        }
    }
}

// ---------------- K2: gate projections ----------------
__global__ void __launch_bounds__(256) k_gate(
    const float* __restrict__ X,
    const float* __restrict__ mdw, const float* __restrict__ mdb,
    const float* __restrict__ sw,  const float* __restrict__ sb,
    const float* __restrict__ lw,  const float* __restrict__ lb)
{
    __shared__ float As[16][68];
    __shared__ float Bg[16][52];
    const int m0 = blockIdx.x * 64;
    const int t = threadIdx.x;
    const int lr = t >> 2, lk = (t & 3) * 4;
    const int ty = t >> 4, tx = t & 15;
    float acc[4][3] = {};
    const float* Arow = X + (size_t)(m0 + lr) * HIDN + lk;
    for (int k0 = 0; k0 < HIDN; k0 += 16){
        float4 av = *(const float4*)(Arow + k0);
        As[lk+0][lr]=av.x; As[lk+1][lr]=av.y; As[lk+2][lr]=av.z; As[lk+3][lr]=av.w;
        if (t < 192){
#pragma unroll
            for (int j = 0; j < 4; j++){
                int idx = t*4+j, n = idx>>4, k = idx&15;
                const float* wp = (n<16)?(mdw+(size_t)n*HIDN):(n<32)?(sw+(size_t)(n-16)*HIDN):(lw+(size_t)(n-32)*HIDN);
                Bg[k][n] = wp[k0+k];
            }
        }
        __syncthreads();
#pragma unroll
        for (int kk = 0; kk < 16; kk++){
            float4 a = *(const float4*)&As[kk][ty*4];
            float ar[4] = {a.x,a.y,a.z,a.w};
            float b0=Bg[kk][tx*3], b1=Bg[kk][tx*3+1], b2=Bg[kk][tx*3+2];
#pragma unroll
            for (int i = 0; i < 4; i++){ acc[i][0]+=ar[i]*b0; acc[i][1]+=ar[i]*b1; acc[i][2]+=ar[i]*b2; }
        }
        __syncthreads();
    }
#pragma unroll
    for (int i = 0; i < 4; i++)
#pragma unroll
        for (int j = 0; j < 3; j++){
            int m = m0 + ty*4 + i, o = tx*3 + j;
            float bias = (o<16)?mdb[o]:(o<32)?sb[o-16]:lb[o-32];
            float v = sigmf(acc[i][j] + bias);
            int bc = m >> 12, l = m & (LL-1), g = o >> 4, hh = o & 15;
            g_gate[(size_t)g*NGATE + ((size_t)(bc*HH+hh))*LL + l] = (g==0)?(1.0f-v):v;
        }
}

// ---------------- K3: causal conv + silu (+rmsnorm), 8 timesteps/block ----------------
#define CT 8
__global__ void __launch_bounds__(256) k_conv(
    const float* __restrict__ cqw, const float* __restrict__ cqb,
    const float* __restrict__ ckw, const float* __restrict__ ckb,
    const float* __restrict__ cvw, const float* __restrict__ cvb,
    const float* __restrict__ qnw, const float* __restrict__ knw)
{
    const int z = blockIdx.z, b = blockIdx.y, l0 = blockIdx.x*CT;
    const float* w    = (z==0)?cqw:(z==1)?ckw:cvw;
    const float* bias = (z==0)?cqb:(z==1)?ckb:cvb;
    const float* src = g_qkv + (size_t)z*MM*HIDN + (size_t)b*LL*HIDN;
    __shared__ float rows[CT+3][1024];
    __shared__ float hs[CT*16];
    const int t = threadIdx.x;
    if (t < CT*16) hs[t] = 0.0f;
    for (int e = t; e < (CT+3)*256; e += 256){
        int j = e>>8, c4 = (e&255)*4;
        int ls = l0 - 3 + j;
        float4 v = (ls >= 0) ? *(const float4*)(src + (size_t)ls*HIDN + c4) : make_float4(0,0,0,0);
        *(float4*)&rows[j][c4] = v;
    }
    __syncthreads();
    const int c0 = t*4, head = c0>>6, d0 = c0&63;
    float4 w0 = *(const float4*)&w[(c0+0)*4];
    float4 w1 = *(const float4*)&w[(c0+1)*4];
    float4 w2 = *(const float4*)&w[(c0+2)*4];
    float4 w3 = *(const float4*)&w[(c0+3)*4];
    float4 bz = *(const float4*)&bias[c0];
    float y[CT][4];
#pragma unroll
    for (int li = 0; li < CT; li++){
        float a0=bz.x, a1=bz.y, a2=bz.z, a3=bz.w;
#pragma unroll
        for (int k = 0; k < 4; k++){
            float4 x = *(const float4*)&rows[li + k][c0];
            float wk0 = ((const float*)&w0)[k], wk1 = ((const float*)&w1)[k];
            float wk2 = ((const float*)&w2)[k], wk3 = ((const float*)&w3)[k];
            a0 += wk0*x.x; a1 += wk1*x.y; a2 += wk2*x.z; a3 += wk3*x.w;
        }
        a0 *= sigmf(a0); a1 *= sigmf(a1); a2 *= sigmf(a2); a3 *= sigmf(a3);
        y[li][0]=a0; y[li][1]=a1; y[li][2]=a2; y[li][3]=a3;
        if (z < 2) atomicAdd(&hs[li*16+head], a0*a0+a1*a1+a2*a2+a3*a3);
    }
    __syncthreads();
#pragma unroll
    for (int li = 0; li < CT; li++){
        float4 o;
        if (z < 2){
            float sc = rsqrtf(hs[li*16+head]*(1.0f/64.0f) + EPSF);
            const float* nw = (z==0)?qnw:knw;
            o = make_float4(y[li][0]*sc*nw[d0], y[li][1]*sc*nw[d0+1], y[li][2]*sc*nw[d0+2], y[li][3]*sc*nw[d0+3]);
        } else {
            o = make_float4(y[li][0], y[li][1], y[li][2], y[li][3]);
        }
        *(float4*)(g_proc + (size_t)z*NPROC + (((size_t)(b*HH+head))*LL + l0+li)*DD + d0) = o;
    }
}

// ---------------- K4: chunked scan, weighted-sum folds ----------------
#define OW1 0
#define OW2 8448
#define OW2T 17152
#define OZ1 25600
#define OX1 34048
#define OKT 42496
#define OGT 46848
#define OPA 51200
#define OPW2 53248
#define OPKM 54272
#define OVV 54784
#define SCAN_BYTES ((OVV + 706)*4)

__global__ void __launch_bounds__(512,1) k_scan(
    const float* __restrict__ W1g, const float* __restrict__ W2g, float* __restrict__ out)
{
    extern __shared__ float sm[];
    float* sW1  = sm + OW1;   // [64][132]
    float* sW2  = sm + OW2;   // [128][68]
    float* sW2T = sm + OW2T;  // [64][132]
    float* sZ1  = sm + OZ1;   // [64][132]
    float* sX1  = sm + OX1;   // [64][132]
    float* sKT  = sm + OKT;   // [64][68] kc^T / qc^T
    float* sGT  = sm + OGT;   // [64][68] g0^T / y^T
    float* pA   = sm + OPA;   // [16][128] pXm then pW1s
    float* pW2  = sm + OPW2;  // [16][64]
    float* pKm  = sm + OPKM;  // [8][64]
    float* sW1s = sm + OVV;  float* sW2s = sW1s+128; float* sKm = sW2s+64;
    float* sXm  = sKm+64;    float* sMd  = sXm+128;  float* sSd = sMd+64;
    float* sLr  = sSd+64;    float* sWt  = sLr+64;   float* sWs = sWt+64;
    float* sMp  = sWs+64;    // [2]

    const int t = threadIdx.x;
    const int bh = blockIdx.x, b = bh >> 4, h = bh & 15;
    const float* qp = g_proc + 0*NPROC + (size_t)bh*LL*DD;
    const float* kp = g_proc + 1*NPROC + (size_t)bh*LL*DD;
    const float* vp = g_proc + 2*NPROC + (size_t)bh*LL*DD;
    const float* gmd = g_gate + 0*NGATE + (size_t)bh*LL;
    const float* gsd = g_gate + 1*NGATE + (size_t)bh*LL;
    const float* glr = g_gate + 2*NGATE + (size_t)bh*LL;

    for (int e = t; e < DD*DMM; e += 512){ int d=e>>7, c=e&127; sW1[d*132+c] = W1g[(size_t)h*DD*DMM+e]; }
    for (int e = t; e < DMM*DD; e += 512){ int c=e>>6, d=e&63; float v=W2g[(size_t)h*DMM*DD+e]; sW2[c*68+d]=v; sW2T[d*132+c]=v; }
    if (t < 128){ sW1s[t]=0.0f; sXm[t]=0.0f; }
    if (t < 64){ sW2s[t]=0.0f; sKm[t]=0.0f; sMd[t]=gmd[t]; sSd[t]=gsd[t]; sLr[t]=glr[t]; }
    __syncthreads();

    const int rg = t>>5;
    const int r0 = rg*4;
    const int c0 = (t&31)*4;
    const int c2 = (t&31)*2;

    for (int ch = 0; ch < NCH; ch++){
        const int l0 = ch*CSZ;
        // --- A: load kc^T, vc->regs; weights ---
        float vcr[4][2];
        for (int e = t; e < CSZ*DD; e += 512){
            int i = e>>6, d = e&63;
            sKT[d*68+i] = kp[(size_t)(l0+i)*DD + d];
        }
#pragma unroll
        for (int i = 0; i < 4; i++){
            float2 vv = *(const float2*)(vp + (size_t)(l0+r0+i)*DD + c2);
            vcr[i][0]=vv.x; vcr[i][1]=vv.y;
        }
        if (t == 504){
            float w2c = 1.0f; sWt[63] = 1.0f;
            for (int j = 62; j >= 0; j--){ w2c *= sMd[j+1]; sWt[j] = w2c; }
            sMp[0] = w2c * sMd[0];
        } else if (t == 505){
            float w2c = 1.0f; sWs[63] = 1.0f;
            for (int j = 62; j >= 0; j--){ w2c *= sSd[j+1]; sWs[j] = w2c; }
            sMp[1] = w2c * sSd[0];
        }
        __syncthreads();

        // --- B: Z1 = kc@W1, X1 = silu(Z1); fold pXm, pKm ---
        {
            ull acc[4][2] = {};
            for (int d = 0; d < DD; d++){
                float4 a = *(const float4*)&sKT[d*68+r0];
                ull a0=dup2(a.x),a1=dup2(a.y),a2=dup2(a.z),a3=dup2(a.w);
                ulonglong2 bv = *(const ulonglong2*)&sW1[d*132+c0];
                FMA2(acc[0][0],a0,bv.x); FMA2(acc[0][1],a0,bv.y);
                FMA2(acc[1][0],a1,bv.x); FMA2(acc[1][1],a1,bv.y);
                FMA2(acc[2][0],a2,bv.x); FMA2(acc[2][1],a2,bv.y);
                FMA2(acc[3][0],a3,bv.x); FMA2(acc[3][1],a3,bv.y);
            }
            float px[4] = {0,0,0,0};
#pragma unroll
            for (int i = 0; i < 4; i++){
                float2 p = unp(acc[i][0]), qq = unp(acc[i][1]);
                float xv[4] = {p.x*sigmf(p.x), p.y*sigmf(p.y), qq.x*sigmf(qq.x), qq.y*sigmf(qq.y)};
                *(float4*)&sZ1[(r0+i)*132+c0] = make_float4(p.x,p.y,qq.x,qq.y);
                *(float4*)&sX1[(r0+i)*132+c0] = make_float4(xv[0],xv[1],xv[2],xv[3]);
                float wv = sWt[r0+i];
#pragma unroll
                for (int j = 0; j < 4; j++) px[j] += wv*xv[j];
            }
            *(float4*)&pA[rg*128+c0] = make_float4(px[0],px[1],px[2],px[3]);
            int i0 = (t>>6)*8, dd = t&63;
            float4 ka = *(const float4*)&sKT[dd*68+i0];
            float4 kb = *(const float4*)&sKT[dd*68+i0+4];
            pKm[(t>>6)*64+dd] = sWt[i0]*ka.x + sWt[i0+1]*ka.y + sWt[i0+2]*ka.z + sWt[i0+3]*ka.w
                              + sWt[i0+4]*kb.x + sWt[i0+5]*kb.y + sWt[i0+6]*kb.z + sWt[i0+7]*kb.w;
        }
        __syncthreads();

        // --- C: g0 = X1@W2 - vc -> sGT; fold pW2s; reduce sXm,sKm ---
        {
            ull acc[4] = {};
            for (int cc = 0; cc < DMM; cc += 4){
                float4 a0 = *(const float4*)&sX1[(r0+0)*132+cc];
                float4 a1 = *(const float4*)&sX1[(r0+1)*132+cc];
                float4 a2 = *(const float4*)&sX1[(r0+2)*132+cc];
                float4 a3 = *(const float4*)&sX1[(r0+3)*132+cc];
#pragma unroll
                for (int u = 0; u < 4; u++){
                    ull bv = *(const ull*)&sW2[(cc+u)*68+c2];
                    float e0 = u==0?a0.x:u==1?a0.y:u==2?a0.z:a0.w;
                    float e1 = u==0?a1.x:u==1?a1.y:u==2?a1.z:a1.w;
                    float e2 = u==0?a2.x:u==1?a2.y:u==2?a2.z:a2.w;
                    float e3 = u==0?a3.x:u==1?a3.y:u==2?a3.z:a3.w;
                    FMA2(acc[0],dup2(e0),bv); FMA2(acc[1],dup2(e1),bv);
                    FMA2(acc[2],dup2(e2),bv); FMA2(acc[3],dup2(e3),bv);
                }
            }
            float pw[2] = {0,0};
#pragma unroll
            for (int i = 0; i < 4; i++){
                float2 p = unp(acc[i]);
                float g0 = p.x - vcr[i][0], g1 = p.y - vcr[i][1];
                sGT[(c2+0)*68+(r0+i)] = g0;
                sGT[(c2+1)*68+(r0+i)] = g1;
                float wl = sWs[r0+i] * (-sLr[r0+i]);
                pw[0] += wl*g0; pw[1] += wl*g1;
            }
            *(float2*)&pW2[rg*64+c2] = make_float2(pw[0], pw[1]);
            if (t < 128){
                float s = sMp[0]*sXm[t];
#pragma unroll
                for (int g = 0; g < 16; g++) s += pA[g*128+t];
                sXm[t] = s;
            } else if (t < 192){
                int d = t-128;
                float s = sMp[0]*sKm[d];
#pragma unroll
                for (int g = 0; g < 8; g++) s += pKm[g*64+d];
                sKm[d] = s;
            }
        }
        __syncthreads();

        // --- E: gZ1 = -lr*(g0@W2^T)*silu_bwd(Z1); fold pW1s only ---
        {
            ull acc[4][2] = {};
            for (int d = 0; d < DD; d++){
                float4 a = *(const float4*)&sGT[d*68+r0];
                ull a0=dup2(a.x),a1=dup2(a.y),a2=dup2(a.z),a3=dup2(a.w);
                ulonglong2 bv = *(const ulonglong2*)&sW2T[d*132+c0];
                FMA2(acc[0][0],a0,bv.x); FMA2(acc[0][1],a0,bv.y);
                FMA2(acc[1][0],a1,bv.x); FMA2(acc[1][1],a1,bv.y);
                FMA2(acc[2][0],a2,bv.x); FMA2(acc[2][1],a2,bv.y);
                FMA2(acc[3][0],a3,bv.x); FMA2(acc[3][1],a3,bv.y);
            }
            float pw[4] = {0,0,0,0};
#pragma unroll
            for (int i = 0; i < 4; i++){
                float nlr = -sLr[r0+i];
                float ws = sWs[r0+i];
                float2 p = unp(acc[i][0]), qq = unp(acc[i][1]);
                float g[4] = {p.x,p.y,qq.x,qq.y};
#pragma unroll
                for (int j = 0; j < 4; j++){
                    float z = sZ1[(r0+i)*132+c0+j];
                    float sg = sigmf(z);
                    float gz = nlr*g[j]*(sg*(1.0f + z*(1.0f - sg)));
                    pw[j] += ws*gz;
                }
            }
            *(float4*)&pA[rg*128+c0] = make_float4(pw[0],pw[1],pw[2],pw[3]);
        }
        __syncthreads();

        // --- G1: reduce pW1s, pW2s ---
        if (t < 128){
            float s = sMp[1]*sW1s[t];
#pragma unroll
            for (int g = 0; g < 16; g++) s += pA[g*128+t];
            sW1s[t] = s;
        } else if (t < 192){
            int d = t-128;
            float s = sMp[1]*sW2s[d];
#pragma unroll
            for (int g = 0; g < 16; g++) s += pW2[g*64+d];
            sW2s[d] = s;
        }
        __syncthreads();

        // --- G2: update W1/W2/W2T; load qc^T ---
        {
            float mp = sMp[0];
            for (int e = t; e < DD*DMM; e += 512){
                int d = e>>7, c = e&127;
                sW1[d*132+c] = mp*sW1[d*132+c] + sKm[d]*sW1s[c];
            }
            for (int e = t; e < DMM*DD; e += 512){
                int c = e>>6, d = e&63;
                float v = mp*sW2[c*68+d] + sXm[c]*sW2s[d];
                sW2[c*68+d] = v; sW2T[d*132+c] = v;
            }
            for (int e = t; e < CSZ*DD; e += 512){
                int i = e>>6, d = e&63;
                sKT[d*68+i] = qp[(size_t)(l0+i)*DD + d];
            }
        }
        __syncthreads();

        // --- H: Zq = qc@W1n ; silu -> sZ1 ---
        {
            ull acc[4][2] = {};
            for (int d = 0; d < DD; d++){
                float4 a = *(const float4*)&sKT[d*68+r0];
                ull a0=dup2(a.x),a1=dup2(a.y),a2=dup2(a.z),a3=dup2(a.w);
                ulonglong2 bv = *(const ulonglong2*)&sW1[d*132+c0];
                FMA2(acc[0][0],a0,bv.x); FMA2(acc[0][1],a0,bv.y);
                FMA2(acc[1][0],a1,bv.x); FMA2(acc[1][1],a1,bv.y);
                FMA2(acc[2][0],a2,bv.x); FMA2(acc[2][1],a2,bv.y);
                FMA2(acc[3][0],a3,bv.x); FMA2(acc[3][1],a3,bv.y);
            }
#pragma unroll
            for (int i = 0; i < 4; i++){
                float2 p = unp(acc[i][0]), qq = unp(acc[i][1]);
                *(float4*)&sZ1[(r0+i)*132+c0] =
                    make_float4(p.x*sigmf(p.x), p.y*sigmf(p.y), qq.x*sigmf(qq.x), qq.y*sigmf(qq.y));
            }
        }
        __syncthreads();

        // --- I: y = silu(Zq)@W2n -> sGT ---
        {
            ull acc[4] = {};
            for (int cc = 0; cc < DMM; cc += 4){
                float4 a0 = *(const float4*)&sZ1[(r0+0)*132+cc];
                float4 a1 = *(const float4*)&sZ1[(r0+1)*132+cc];
                float4 a2 = *(const float4*)&sZ1[(r0+2)*132+cc];
                float4 a3 = *(const float4*)&sZ1[(r0+3)*132+cc];
#pragma unroll
                for (int u = 0; u < 4; u++){
                    ull bv = *(const ull*)&sW2[(cc+u)*68+c2];
                    float e0 = u==0?a0.x:u==1?a0.y:u==2?a0.z:a0.w;
                    float e1 = u==0?a1.x:u==1?a1.y:u==2?a1.z:a1.w;
                    float e2 = u==0?a2.x:u==1?a2.y:u==2?a2.z:a2.w;
                    float e3 = u==0?a3.x:u==1?a3.y:u==2?a3.z:a3.w;
                    FMA2(acc[0],dup2(e0),bv); FMA2(acc[1],dup2(e1),bv);
                    FMA2(acc[2],dup2(e2),bv); FMA2(acc[3],dup2(e3),bv);
                }
            }
#pragma unroll
            for (int i = 0; i < 4; i++){
                float2 p = unp(acc[i]);
                sGT[(c2+0)*68+(r0+i)] = p.x;
                sGT[(c2+1)*68+(r0+i)] = p.y;
            }
        }
        __syncthreads();

        // --- store + prefetch next gates ---
        for (int e = t; e < CSZ*DD; e += 512){
            int d = e>>6, i = e&63;
            out[(size_t)b*LL*HIDN + ((size_t)(h*DD+d))*LL + (l0+i)] = sGT[d*68+i];
        }
        if (ch+1 < NCH && t < CSZ){
            sMd[t] = gmd[l0+CSZ+t]; sSd[t] = gsd[l0+CSZ+t]; sLr[t] = glr[l0+CSZ+t];
        }
        __syncthreads();
    }
}

// ---------------- launch ----------------
extern "C" void kernel_launch(void* const* d_in, const int* in_sizes, int n_in,
                              void* d_out, int out_size) {
    (void)in_sizes; (void)n_in; (void)out_size;
    const float* X   = (const float*)d_in[0];
    const float* Wq  = (const float*)d_in[1];
    const float* Wk  = (const float*)d_in[2];
    const float* Wv  = (const float*)d_in[3];
    const float* cqw = (const float*)d_in[4];
    const float* cqb = (const float*)d_in[5];
    const float* ckw = (const float*)d_in[6];
    const float* ckb = (const float*)d_in[7];
    const float* cvw = (const float*)d_in[8];
    const float* cvb = (const float*)d_in[9];
    const float* qnw = (const float*)d_in[10];
    const float* knw = (const float*)d_in[11];
    const float* mdw = (const float*)d_in[12];
    const float* mdb = (const float*)d_in[13];
    const float* sw  = (const float*)d_in[14];
    const float* sb  = (const float*)d_in[15];
    const float* lw  = (const float*)d_in[16];
    const float* lb  = (const float*)d_in[17];
    const float* W1g = (const float*)d_in[18];
    const float* W2g = (const float*)d_in[19];
    float* out = (float*)d_out;

    cudaFuncSetAttribute(k_qkv, cudaFuncAttributeMaxDynamicSharedMemorySize, QSMEM);
    cudaFuncSetAttribute(k_scan, cudaFuncAttributeMaxDynamicSharedMemorySize, SCAN_BYTES);

    __nv_bfloat16 *xhi, *xlo, *whi, *wlo;
    cudaGetSymbolAddress((void**)&xhi, g_Xhi);
    cudaGetSymbolAddress((void**)&xlo, g_Xlo);
    cudaGetSymbolAddress((void**)&whi, g_Whi);
    cudaGetSymbolAddress((void**)&wlo, g_Wlo);

    k_split<<<MM*HIDN/1024, 256>>>(X, xhi, xlo, MM*HIDN);
    k_split<<<HIDN*HIDN/1024, 256>>>(Wq, whi, wlo, HIDN*HIDN);
    k_split<<<HIDN*HIDN/1024, 256>>>(Wk, whi + (size_t)HIDN*HIDN, wlo + (size_t)HIDN*HIDN, HIDN*HIDN);
    k_split<<<HIDN*HIDN/1024, 256>>>(Wv, whi + (size_t)2*HIDN*HIDN, wlo + (size_t)2*HIDN*HIDN, HIDN*HIDN);
    k_qkv<<<dim3(HIDN/128, MM/128, 3), 256, QSMEM>>>();
    k_gate<<<dim3(MM/64), 256>>>(X, mdw, mdb, sw, sb, lw, lb);
    k_conv<<<dim3(LL/CT, BB, 3), 256>>>(cqw, cqb, ckw, ckb, cvw, cvb, qnw, knw);
    k_scan<<<dim3(BB*HH), 512, SCAN_BYTES>>>(W1g, W2g, out);
}

// round 6
// speedup vs baseline: 2.3073x; 1.0955x over previous
#include <cuda_runtime.h>
#include <cuda_bf16.h>
#include <math.h>
#include <stdint.h>

#define BB 4
#define LL 4096
#define HIDN 1024
#define HH 16
#define DD 64
#define DMM 128
#define CSZ 64
#define NCH 64
#define MM (BB*LL)
#define EPSF 1e-6f
#define NPROC ((size_t)BB*HH*LL*DD)
#define NGATE ((size_t)BB*HH*LL)

static __device__ float g_qkv [(size_t)3*MM*HIDN];
static __device__ float g_proc[(size_t)3*NPROC];
static __device__ float g_gate[(size_t)3*NGATE];
static __device__ __nv_bfloat16 g_Xhi[(size_t)MM*HIDN];
static __device__ __nv_bfloat16 g_Xlo[(size_t)MM*HIDN];
static __device__ __nv_bfloat16 g_Whi[(size_t)3*HIDN*HIDN];
static __device__ __nv_bfloat16 g_Wlo[(size_t)3*HIDN*HIDN];

__device__ __forceinline__ float sigmf(float x){ return __fdividef(1.0f, 1.0f + __expf(-x)); }

typedef unsigned long long ull;
#define FMA2(acc,a,b) asm("fma.rn.f32x2 %0,%1,%2,%0;" : "+l"(acc) : "l"(a), "l"(b))
__device__ __forceinline__ ull dup2(float a){ ull r; asm("mov.b64 %0,{%1,%1};" : "=l"(r) : "r"(__float_as_uint(a))); return r; }
__device__ __forceinline__ float2 unp(ull v){ uint32_t l,h; asm("mov.b64 {%0,%1},%2;" : "=r"(l),"=r"(h) : "l"(v)); return make_float2(__uint_as_float(l),__uint_as_float(h)); }
__device__ __forceinline__ uint32_t smem_u32(const void* p){
    uint32_t a; asm("{ .reg .u64 t; cvta.to.shared.u64 t, %1; cvt.u32.u64 %0, t; }" : "=r"(a) : "l"(p)); return a;
}
__device__ __forceinline__ float ld_peer(uint32_t laddr, uint32_t prank){
    uint32_t ra; float v;
    asm("mapa.shared::cluster.u32 %0,%1,%2;" : "=r"(ra) : "r"(laddr), "r"(prank));
    asm volatile("ld.shared::cluster.f32 %0,[%1];" : "=f"(v) : "r"(ra));
    return v;
}
__device__ __forceinline__ void ldsm4(uint32_t* r, uint32_t a){
    asm volatile("ldmatrix.sync.aligned.m8n8.x4.shared.b16 {%0,%1,%2,%3},[%4];"
        : "=r"(r[0]),"=r"(r[1]),"=r"(r[2]),"=r"(r[3]) : "r"(a));
}
__device__ __forceinline__ void ldsm2(uint32_t* r, uint32_t a){
    asm volatile("ldmatrix.sync.aligned.m8n8.x2.shared.b16 {%0,%1},[%2];"
        : "=r"(r[0]),"=r"(r[1]) : "r"(a));
}
__device__ __forceinline__ void mma16816(float* c, const uint32_t* a, const uint32_t* b){
    asm volatile("mma.sync.aligned.m16n8k16.row.col.f32.bf16.bf16.f32 "
        "{%0,%1,%2,%3},{%4,%5,%6,%7},{%8,%9},{%0,%1,%2,%3};"
        : "+f"(c[0]),"+f"(c[1]),"+f"(c[2]),"+f"(c[3])
        : "r"(a[0]),"r"(a[1]),"r"(a[2]),"r"(a[3]),"r"(b[0]),"r"(b[1]));
}
#define CPA(dst,src) asm volatile("cp.async.cg.shared.global [%0],[%1],16;" :: "r"(dst),"l"(src))
#define CPC() asm volatile("cp.async.commit_group;" ::: "memory")
#define CPW(n) asm volatile("cp.async.wait_group %0;" :: "n"(n) : "memory")

// ---------------- K0: fp32 -> bf16 hi/lo ----------------
__global__ void __launch_bounds__(256) k_split(const float* __restrict__ src,
    __nv_bfloat16* __restrict__ hi, __nv_bfloat16* __restrict__ lo, int n)
{
    int i = (blockIdx.x*256 + threadIdx.x)*4;
    if (i >= n) return;
    float4 v = *(const float4*)(src + i);
    float f[4] = {v.x,v.y,v.z,v.w};
    __nv_bfloat16 h[4], l[4];
#pragma unroll
    for (int j = 0; j < 4; j++){
        h[j] = __float2bfloat16_rn(f[j]);
        l[j] = __float2bfloat16_rn(f[j] - __bfloat162float(h[j]));
    }
    *(__nv_bfloat162*)(hi+i)   = __halves2bfloat162(h[0],h[1]);
    *(__nv_bfloat162*)(hi+i+2) = __halves2bfloat162(h[2],h[3]);
    *(__nv_bfloat162*)(lo+i)   = __halves2bfloat162(l[0],l[1]);
    *(__nv_bfloat162*)(lo+i+2) = __halves2bfloat162(l[2],l[3]);
}

// ---------------- K1: qkv GEMM, mma.sync bf16 3-term, cp.async 4-stage ----------------
#define STG_B 24576
#define QSMEM (4*STG_B)

__global__ void __launch_bounds__(256) k_qkv()
{
    extern __shared__ __align__(16) char qs[];
    const int t = threadIdx.x, wid = t>>5, lam = t&31;
    const int z = blockIdx.z, n0 = blockIdx.x*128, m0 = blockIdx.y*128;
    const uint32_t sb = smem_u32(qs);
    const int r = t>>1, q = t&1;
    const __nv_bfloat16* Ah = g_Xhi + (size_t)(m0+r)*HIDN + q*8;
    const __nv_bfloat16* Al = g_Xlo + (size_t)(m0+r)*HIDN + q*8;
    const __nv_bfloat16* Bh = g_Whi + (size_t)z*HIDN*HIDN + (size_t)(n0+r)*HIDN + q*8;
    const __nv_bfloat16* Bl = g_Wlo + (size_t)z*HIDN*HIDN + (size_t)(n0+r)*HIDN + q*8;
    const uint32_t soff = (uint32_t)(r*48 + q*16);

    float acc[4][4][4] = {};
    const int wm = (wid>>2)*64, wn = (wid&3)*32;
    const uint32_t a_l = (uint32_t)((lam & 15)*48 + (lam>>4)*16);
    const uint32_t b_l = (uint32_t)((lam & 7)*48 + ((lam>>3)&1)*16);

#define ISSUE(s_) do{ uint32_t ds = sb + (uint32_t)(((s_)&3)*STG_B) + soff; int k0 = (s_)*16; \
    CPA(ds,       Ah + k0); CPA(ds+6144,  Al + k0); \
    CPA(ds+12288, Bh + k0); CPA(ds+18432, Bl + k0); CPC(); }while(0)

    ISSUE(0); ISSUE(1); ISSUE(2);
    for (int s = 0; s < 64; s++){
        CPW(2);
        __syncthreads();
        if (s < 61) ISSUE(s+3); else CPC();
        uint32_t cb = sb + (uint32_t)((s&3)*STG_B);
        uint32_t ah[4][4], al[4][4], bh[4][2], bl[4][2];
#pragma unroll
        for (int mi = 0; mi < 4; mi++){
            uint32_t rowb = cb + (uint32_t)(wm + mi*16)*48 + a_l;
            ldsm4(ah[mi], rowb); ldsm4(al[mi], rowb + 6144);
        }
#pragma unroll
        for (int ni = 0; ni < 4; ni++){
            uint32_t rowb = cb + 12288 + (uint32_t)(wn + ni*8)*48 + b_l;
            ldsm2(bh[ni], rowb); ldsm2(bl[ni], rowb + 6144);
        }
#pragma unroll
        for (int mi = 0; mi < 4; mi++)
#pragma unroll
            for (int ni = 0; ni < 4; ni++){
                mma16816(acc[mi][ni], ah[mi], bh[ni]);
                mma16816(acc[mi][ni], ah[mi], bl[ni]);
                mma16816(acc[mi][ni], al[mi], bh[ni]);
            }
    }
#undef ISSUE
    float* C = g_qkv + (size_t)z*MM*HIDN;
    const int rr = lam>>2, cc2 = (lam&3)*2;
#pragma unroll
    for (int mi = 0; mi < 4; mi++){
        int row0 = m0 + wm + mi*16 + rr;
#pragma unroll
        for (int ni = 0; ni < 4; ni++){
            int col = n0 + wn + ni*8 + cc2;
            *(float2*)&C[(size_t)row0*HIDN + col]     = make_float2(acc[mi][ni][0], acc[mi][ni][1]);
            *(float2*)&C[(size_t)(row0+8)*HIDN + col] = make_float2(acc[mi][ni][2], acc[mi][ni][3]);
        }
    }
}

// ---------------- K2: gate projections ----------------
__global__ void __launch_bounds__(256) k_gate(
    const float* __restrict__ X,
    const float* __restrict__ mdw, const float* __restrict__ mdb,
    const float* __restrict__ sw,  const float* __restrict__ sb,
    const float* __restrict__ lw,  const float* __restrict__ lb)
{
    __shared__ float As[16][68];
    __shared__ float Bg[16][52];
    const int m0 = blockIdx.x * 64;
    const int t = threadIdx.x;
    const int lr = t >> 2, lk = (t & 3) * 4;
    const int ty = t >> 4, tx = t & 15;
    float acc[4][3] = {};
    const float* Arow = X + (size_t)(m0 + lr) * HIDN + lk;
    for (int k0 = 0; k0 < HIDN; k0 += 16){
        float4 av = *(const float4*)(Arow + k0);
        As[lk+0][lr]=av.x; As[lk+1][lr]=av.y; As[lk+2][lr]=av.z; As[lk+3][lr]=av.w;
        if (t < 192){
#pragma unroll
            for (int j = 0; j < 4; j++){
                int idx = t*4+j, n = idx>>4, k = idx&15;
                const float* wp = (n<16)?(mdw+(size_t)n*HIDN):(n<32)?(sw+(size_t)(n-16)*HIDN):(lw+(size_t)(n-32)*HIDN);
                Bg[k][n] = wp[k0+k];
            }
        }
        __syncthreads();
#pragma unroll
        for (int kk = 0; kk < 16; kk++){
            float4 a = *(const float4*)&As[kk][ty*4];
            float ar[4] = {a.x,a.y,a.z,a.w};
            float b0=Bg[kk][tx*3], b1=Bg[kk][tx*3+1], b2=Bg[kk][tx*3+2];
#pragma unroll
            for (int i = 0; i < 4; i++){ acc[i][0]+=ar[i]*b0; acc[i][1]+=ar[i]*b1; acc[i][2]+=ar[i]*b2; }
        }
        __syncthreads();
    }
#pragma unroll
    for (int i = 0; i < 4; i++)
#pragma unroll
        for (int j = 0; j < 3; j++){
            int m = m0 + ty*4 + i, o = tx*3 + j;
            float bias = (o<16)?mdb[o]:(o<32)?sb[o-16]:lb[o-32];
            float v = sigmf(acc[i][j] + bias);
            int bc = m >> 12, l = m & (LL-1), g = o >> 4, hh = o & 15;
            g_gate[(size_t)g*NGATE + ((size_t)(bc*HH+hh))*LL + l] = (g==0)?(1.0f-v):v;
        }
}

// ---------------- K3: causal conv + silu (+rmsnorm), 8 timesteps ----------------
#define CT 8
__global__ void __launch_bounds__(256) k_conv(
    const float* __restrict__ cqw, const float* __restrict__ cqb,
    const float* __restrict__ ckw, const float* __restrict__ ckb,
    const float* __restrict__ cvw, const float* __restrict__ cvb,
    const float* __restrict__ qnw, const float* __restrict__ knw)
{
    const int z = blockIdx.z, b = blockIdx.y, l0 = blockIdx.x*CT;
    const float* w    = (z==0)?cqw:(z==1)?ckw:cvw;
    const float* bias = (z==0)?cqb:(z==1)?ckb:cvb;
    const float* src = g_qkv + (size_t)z*MM*HIDN + (size_t)b*LL*HIDN;
    __shared__ float rows[CT+3][1024];
    __shared__ float hs[CT*16];
    const int t = threadIdx.x;
    if (t < CT*16) hs[t] = 0.0f;
    for (int e = t; e < (CT+3)*256; e += 256){
        int j = e>>8, c4 = (e&255)*4;
        int ls = l0 - 3 + j;
        float4 v = (ls >= 0) ? *(const float4*)(src + (size_t)ls*HIDN + c4) : make_float4(0,0,0,0);
        *(float4*)&rows[j][c4] = v;
    }
    __syncthreads();
    const int c0 = t*4, head = c0>>6, d0 = c0&63;
    float4 w0 = *(const float4*)&w[(c0+0)*4];
    float4 w1 = *(const float4*)&w[(c0+1)*4];
    float4 w2 = *(const float4*)&w[(c0+2)*4];
    float4 w3 = *(const float4*)&w[(c0+3)*4];
    float4 bz = *(const float4*)&bias[c0];
    float y[CT][4];
#pragma unroll
    for (int li = 0; li < CT; li++){
        float a0=bz.x, a1=bz.y, a2=bz.z, a3=bz.w;
#pragma unroll
        for (int k = 0; k < 4; k++){
            float4 x = *(const float4*)&rows[li + k][c0];
            a0 += ((const float*)&w0)[k]*x.x; a1 += ((const float*)&w1)[k]*x.y;
            a2 += ((const float*)&w2)[k]*x.z; a3 += ((const float*)&w3)[k]*x.w;
        }
        a0 *= sigmf(a0); a1 *= sigmf(a1); a2 *= sigmf(a2); a3 *= sigmf(a3);
        y[li][0]=a0; y[li][1]=a1; y[li][2]=a2; y[li][3]=a3;
        if (z < 2) atomicAdd(&hs[li*16+head], a0*a0+a1*a1+a2*a2+a3*a3);
    }
    __syncthreads();
#pragma unroll
    for (int li = 0; li < CT; li++){
        float4 o;
        if (z < 2){
            float sc = rsqrtf(hs[li*16+head]*(1.0f/64.0f) + EPSF);
            const float* nw = (z==0)?qnw:knw;
            o = make_float4(y[li][0]*sc*nw[d0], y[li][1]*sc*nw[d0+1], y[li][2]*sc*nw[d0+2], y[li][3]*sc*nw[d0+3]);
        } else {
            o = make_float4(y[li][0], y[li][1], y[li][2], y[li][3]);
        }
        *(float4*)(g_proc + (size_t)z*NPROC + (((size_t)(b*HH+head))*LL + l0+li)*DD + d0) = o;
    }
}

// ---------------- K4: cluster-2 chunked scan ----------------
#define OW1 0
#define OW2 8448
#define OW2T 17152
#define OZ1 25600
#define OX1 29824
#define OKT 34048
#define OG  36352
#define OPXM 38528
#define OPKM 40576
#define OPW1 40832
#define OPW2 42880
#define OEXC 43904
#define OVV 44672
#define SCAN_BYTES ((OVV + 706)*4)

__global__ void __launch_bounds__(512,1) __cluster_dims__(2,1,1) k_scan(
    const float* __restrict__ W1g, const float* __restrict__ W2g, float* __restrict__ out)
{
    extern __shared__ float sm[];
    float* sW1  = sm + OW1;   // [64][132]
    float* sW2  = sm + OW2;   // [128][68]
    float* sW2T = sm + OW2T;  // [64][132]
    float* sZ1  = sm + OZ1;   // [32][132]
    float* sX1  = sm + OX1;   // [32][132]
    float* sKT  = sm + OKT;   // [64][36] kc^T / qc^T own rows
    float* sG   = sm + OG;    // [32][68] g0 / y own rows
    float* pXm  = sm + OPXM;  // [16][128]
    float* pKm  = sm + OPKM;  // [4][64]
    float* pW1  = sm + OPW1;  // [16][128]
    float* pW2  = sm + OPW2;  // [16][64]
    float* exch = sm + OEXC;  // [2][384]
    float* sW1s = sm + OVV;  float* sW2s = sW1s+128; float* sKm = sW2s+64;
    float* sXm  = sKm+64;    float* sMd  = sXm+128;  float* sSd = sMd+64;
    float* sLr  = sSd+64;    float* sWt  = sLr+64;   float* sWs = sWt+64;
    float* sMp  = sWs+64;

    const int t = threadIdx.x;
    const int bh = blockIdx.x >> 1;
    const uint32_t rank = blockIdx.x & 1, prank = rank ^ 1;
    const int b = bh >> 4, h = bh & 15;
    const int ro = rank*32;  // row offset of this CTA
    const float* qp = g_proc + 0*NPROC + (size_t)bh*LL*DD;
    const float* kp = g_proc + 1*NPROC + (size_t)bh*LL*DD;
    const float* vp = g_proc + 2*NPROC + (size_t)bh*LL*DD;
    const float* gmd = g_gate + 0*NGATE + (size_t)bh*LL;
    const float* gsd = g_gate + 1*NGATE + (size_t)bh*LL;
    const float* glr = g_gate + 2*NGATE + (size_t)bh*LL;

    for (int e = t; e < DD*DMM; e += 512){ int d=e>>7, c=e&127; sW1[d*132+c] = W1g[(size_t)h*DD*DMM+e]; }
    for (int e = t; e < DMM*DD; e += 512){ int c=e>>6, d=e&63; float v=W2g[(size_t)h*DMM*DD+e]; sW2[c*68+d]=v; sW2T[d*132+c]=v; }
    if (t < 128){ sW1s[t]=0.0f; sXm[t]=0.0f; }
    if (t < 64){ sW2s[t]=0.0f; sKm[t]=0.0f; sMd[t]=gmd[t]; sSd[t]=gsd[t]; sLr[t]=glr[t]; }
    __syncthreads();

    const int rg = t>>5;          // warp id = row group (2 rows)
    const int r0 = rg*2;          // local row 0..30
    const int c0 = (t&31)*4;      // 128-wide cols
    const int c2 = (t&31)*2;      // 64-wide cols
    const uint32_t exc_base = smem_u32(exch);

    for (int ch = 0; ch < NCH; ch++){
        const int l0 = ch*CSZ;
        const int par = ch & 1;
        // --- A: load kc^T (own 32 rows), vc->regs, weights ---
        float vcr[2][2];
        for (int e = t; e < 32*64; e += 512){
            int i = e>>6, d = e&63;
            sKT[d*36+i] = kp[(size_t)(l0+ro+i)*DD + d];
        }
#pragma unroll
        for (int i = 0; i < 2; i++){
            float2 vv = *(const float2*)(vp + (size_t)(l0+ro+r0+i)*DD + c2);
            vcr[i][0]=vv.x; vcr[i][1]=vv.y;
        }
        if (t == 504){
            float w2c = 1.0f; sWt[63] = 1.0f;
            for (int j = 62; j >= 0; j--){ w2c *= sMd[j+1]; sWt[j] = w2c; }
            sMp[0] = w2c * sMd[0];
        } else if (t == 505){
            float w2c = 1.0f; sWs[63] = 1.0f;
            for (int j = 62; j >= 0; j--){ w2c *= sSd[j+1]; sWs[j] = w2c; }
            sMp[1] = w2c * sSd[0];
        }
        __syncthreads();

        // --- B: Z1 = kc@W1 (own rows), X1=silu; fold pXm,pKm ---
        {
            ull acc[2][2] = {};
            for (int d = 0; d < DD; d++){
                float2 a = *(const float2*)&sKT[d*36+r0];
                ull a0=dup2(a.x),a1=dup2(a.y);
                ulonglong2 bv = *(const ulonglong2*)&sW1[d*132+c0];
                FMA2(acc[0][0],a0,bv.x); FMA2(acc[0][1],a0,bv.y);
                FMA2(acc[1][0],a1,bv.x); FMA2(acc[1][1],a1,bv.y);
            }
            float px[4] = {0,0,0,0};
#pragma unroll
            for (int i = 0; i < 2; i++){
                float2 p = unp(acc[i][0]), qq = unp(acc[i][1]);
                float xv[4] = {p.x*sigmf(p.x), p.y*sigmf(p.y), qq.x*sigmf(qq.x), qq.y*sigmf(qq.y)};
                *(float4*)&sZ1[(r0+i)*132+c0] = make_float4(p.x,p.y,qq.x,qq.y);
                *(float4*)&sX1[(r0+i)*132+c0] = make_float4(xv[0],xv[1],xv[2],xv[3]);
                float wv = sWt[ro+r0+i];
#pragma unroll
                for (int j = 0; j < 4; j++) px[j] += wv*xv[j];
            }
            *(float4*)&pXm[rg*128+c0] = make_float4(px[0],px[1],px[2],px[3]);
            if (t < 256){
                int i0 = (t>>6)*8, dd = t&63;
                float s = 0.0f;
#pragma unroll
                for (int j = 0; j < 8; j++) s += sWt[ro+i0+j]*sKT[dd*36+i0+j];
                pKm[(t>>6)*64+dd] = s;
            }
        }
        __syncthreads();

        // --- C: g0 = X1@W2 - vc -> sG[i][dd]; fold pW2 ---
        {
            ull acc[2] = {};
            for (int cc = 0; cc < DMM; cc += 4){
                float4 a0 = *(const float4*)&sX1[(r0+0)*132+cc];
                float4 a1 = *(const float4*)&sX1[(r0+1)*132+cc];
#pragma unroll
                for (int u = 0; u < 4; u++){
                    ull bv = *(const ull*)&sW2[(cc+u)*68+c2];
                    float e0 = u==0?a0.x:u==1?a0.y:u==2?a0.z:a0.w;
                    float e1 = u==0?a1.x:u==1?a1.y:u==2?a1.z:a1.w;
                    FMA2(acc[0],dup2(e0),bv); FMA2(acc[1],dup2(e1),bv);
                }
            }
            float pw[2] = {0,0};
#pragma unroll
            for (int i = 0; i < 2; i++){
                float2 p = unp(acc[i]);
                float g0 = p.x - vcr[i][0], g1 = p.y - vcr[i][1];
                *(float2*)&sG[(r0+i)*68+c2] = make_float2(g0, g1);
                float wl = sWs[ro+r0+i] * (-sLr[ro+r0+i]);
                pw[0] += wl*g0; pw[1] += wl*g1;
            }
            *(float2*)&pW2[rg*64+c2] = make_float2(pw[0], pw[1]);
        }
        __syncthreads();

        // --- E: gZ1 = -lr*(g0@W2^T)*silu_bwd(Z1); fold pW1 only ---
        {
            ull acc[2][2] = {};
            for (int d = 0; d < DD; d++){
                float a0s = sG[(r0+0)*68+d], a1s = sG[(r0+1)*68+d];
                ull a0=dup2(a0s), a1=dup2(a1s);
                ulonglong2 bv = *(const ulonglong2*)&sW2T[d*132+c0];
                FMA2(acc[0][0],a0,bv.x); FMA2(acc[0][1],a0,bv.y);
                FMA2(acc[1][0],a1,bv.x); FMA2(acc[1][1],a1,bv.y);
            }
            float pw[4] = {0,0,0,0};
#pragma unroll
            for (int i = 0; i < 2; i++){
                float nlr = -sLr[ro+r0+i];
                float ws = sWs[ro+r0+i];
                float2 p = unp(acc[i][0]), qq = unp(acc[i][1]);
                float g[4] = {p.x,p.y,qq.x,qq.y};
#pragma unroll
                for (int j = 0; j < 4; j++){
                    float z = sZ1[(r0+i)*132+c0+j];
                    float sg = sigmf(z);
                    pw[j] += ws * (nlr*g[j]*(sg*(1.0f + z*(1.0f - sg))));
                }
            }
            *(float4*)&pW1[rg*128+c0] = make_float4(pw[0],pw[1],pw[2],pw[3]);
        }
        __syncthreads();

        // --- R1: local reduce -> exch[par] ---
        if (t < 384){
            float s = 0.0f;
            if (t < 128){
#pragma unroll
                for (int g = 0; g < 16; g++) s += pXm[g*128+t];
            } else if (t < 192){
                int d = t-128;
#pragma unroll
                for (int g = 0; g < 4; g++) s += pKm[g*64+d];
            } else if (t < 320){
                int c = t-192;
#pragma unroll
                for (int g = 0; g < 16; g++) s += pW1[g*128+c];
            } else {
                int d = t-320;
#pragma unroll
                for (int g = 0; g < 16; g++) s += pW2[g*64+d];
            }
            exch[par*384 + t] = s;
        }
        asm volatile("barrier.cluster.arrive.aligned;" ::: "memory");
        asm volatile("barrier.cluster.wait.aligned;" ::: "memory");

        // --- R2: cross-CTA sum (rank0 first), update carries ---
        if (t < 384){
            float ov = exch[par*384 + t];
            float pv = ld_peer(exc_base + (uint32_t)(par*384 + t)*4u, prank);
            float v0 = (rank == 0) ? ov : pv;
            float v1 = (rank == 0) ? pv : ov;
            float total = v0 + v1;
            if (t < 128)       sXm[t]      = sMp[0]*sXm[t]      + total;
            else if (t < 192)  sKm[t-128]  = sMp[0]*sKm[t-128]  + total;
            else if (t < 320)  sW1s[t-192] = sMp[1]*sW1s[t-192] + total;
            else               sW2s[t-320] = sMp[1]*sW2s[t-320] + total;
        }
        __syncthreads();

        // --- G2: W updates (duplicated, deterministic); load qc^T ---
        {
            float mp = sMp[0];
            for (int e = t; e < DD*DMM; e += 512){
                int d = e>>7, c = e&127;
                sW1[d*132+c] = mp*sW1[d*132+c] + sKm[d]*sW1s[c];
            }
            for (int e = t; e < DMM*DD; e += 512){
                int c = e>>6, d = e&63;
                float v = mp*sW2[c*68+d] + sXm[c]*sW2s[d];
                sW2[c*68+d] = v; sW2T[d*132+c] = v;
            }
            for (int e = t; e < 32*64; e += 512){
                int i = e>>6, d = e&63;
                sKT[d*36+i] = qp[(size_t)(l0+ro+i)*DD + d];
            }
        }
        __syncthreads();

        // --- H: Zq = qc@W1n ; silu -> sZ1 ---
        {
            ull acc[2][2] = {};
            for (int d = 0; d < DD; d++){
                float2 a = *(const float2*)&sKT[d*36+r0];
                ull a0=dup2(a.x),a1=dup2(a.y);
                ulonglong2 bv = *(const ulonglong2*)&sW1[d*132+c0];
                FMA2(acc[0][0],a0,bv.x); FMA2(acc[0][1],a0,bv.y);
                FMA2(acc[1][0],a1,bv.x); FMA2(acc[1][1],a1,bv.y);
            }
#pragma unroll
            for (int i = 0; i < 2; i++){
                float2 p = unp(acc[i][0]), qq = unp(acc[i][1]);
                *(float4*)&sZ1[(r0+i)*132+c0] =
                    make_float4(p.x*sigmf(p.x), p.y*sigmf(p.y), qq.x*sigmf(qq.x), qq.y*sigmf(qq.y));
            }
        }
        __syncthreads();

        // --- I: y = silu(Zq)@W2n -> sG[i][dd] ---
        {
            ull acc[2] = {};
            for (int cc = 0; cc < DMM; cc += 4){
                float4 a0 = *(const float4*)&sZ1[(r0+0)*132+cc];
                float4 a1 = *(const float4*)&sZ1[(r0+1)*132+cc];
#pragma unroll
                for (int u = 0; u < 4; u++){
                    ull bv = *(const ull*)&sW2[(cc+u)*68+c2];
                    float e0 = u==0?a0.x:u==1?a0.y:u==2?a0.z:a0.w;
                    float e1 = u==0?a1.x:u==1?a1.y:u==2?a1.z:a1.w;
                    FMA2(acc[0],dup2(e0),bv); FMA2(acc[1],dup2(e1),bv);
                }
            }
#pragma unroll
            for (int i = 0; i < 2; i++){
                float2 p = unp(acc[i]);
                *(float2*)&sG[(r0+i)*68+c2] = make_float2(p.x, p.y);
            }
        }
        __syncthreads();

        // --- store own rows + prefetch next gates ---
        for (int e = t; e < 32*64; e += 512){
            int d = e>>5, i = e&31;
            out[(size_t)b*LL*HIDN + ((size_t)(h*DD+d))*LL + (l0+ro+i)] = sG[i*68+d];
        }
        if (ch+1 < NCH && t < CSZ){
            sMd[t] = gmd[l0+CSZ+t]; sSd[t] = gsd[l0+CSZ+t]; sLr[t] = glr[l0+CSZ+t];
        }
        __syncthreads();
    }
}

// ---------------- launch ----------------
extern "C" void kernel_launch(void* const* d_in, const int* in_sizes, int n_in,
                              void* d_out, int out_size) {
    (void)in_sizes; (void)n_in; (void)out_size;
    const float* X   = (const float*)d_in[0];
    const float* Wq  = (const float*)d_in[1];
    const float* Wk  = (const float*)d_in[2];
    const float* Wv  = (const float*)d_in[3];
    const float* cqw = (const float*)d_in[4];
    const float* cqb = (const float*)d_in[5];
    const float* ckw = (const float*)d_in[6];
    const float* ckb = (const float*)d_in[7];
    const float* cvw = (const float*)d_in[8];
    const float* cvb = (const float*)d_in[9];
    const float* qnw = (const float*)d_in[10];
    const float* knw = (const float*)d_in[11];
    const float* mdw = (const float*)d_in[12];
    const float* mdb = (const float*)d_in[13];
    const float* sw  = (const float*)d_in[14];
    const float* sb  = (const float*)d_in[15];
    const float* lw  = (const float*)d_in[16];
    const float* lb  = (const float*)d_in[17];
    const float* W1g = (const float*)d_in[18];
    const float* W2g = (const float*)d_in[19];
    float* out = (float*)d_out;

    cudaFuncSetAttribute(k_qkv, cudaFuncAttributeMaxDynamicSharedMemorySize, QSMEM);
    cudaFuncSetAttribute(k_scan, cudaFuncAttributeMaxDynamicSharedMemorySize, SCAN_BYTES);

    __nv_bfloat16 *xhi, *xlo, *whi, *wlo;
    cudaGetSymbolAddress((void**)&xhi, g_Xhi);
    cudaGetSymbolAddress((void**)&xlo, g_Xlo);
    cudaGetSymbolAddress((void**)&whi, g_Whi);
    cudaGetSymbolAddress((void**)&wlo, g_Wlo);

    k_split<<<MM*HIDN/1024, 256>>>(X, xhi, xlo, MM*HIDN);
    k_split<<<HIDN*HIDN/1024, 256>>>(Wq, whi, wlo, HIDN*HIDN);
    k_split<<<HIDN*HIDN/1024, 256>>>(Wk, whi + (size_t)HIDN*HIDN, wlo + (size_t)HIDN*HIDN, HIDN*HIDN);
    k_split<<<HIDN*HIDN/1024, 256>>>(Wv, whi + (size_t)2*HIDN*HIDN, wlo + (size_t)2*HIDN*HIDN, HIDN*HIDN);
    k_qkv<<<dim3(HIDN/128, MM/128, 3), 256, QSMEM>>>();
    k_gate<<<dim3(MM/64), 256>>>(X, mdw, mdb, sw, sb, lw, lb);
    k_conv<<<dim3(LL/CT, BB, 3), 256>>>(cqw, cqb, ckw, ckb, cvw, cvb, qnw, knw);
    k_scan<<<dim3(BB*HH*2), 512, SCAN_BYTES>>>(W1g, W2g, out);
}

// round 7
// speedup vs baseline: 2.5896x; 1.1224x over previous
#include <cuda_runtime.h>
#include <cuda_bf16.h>
#include <math.h>
#include <stdint.h>

#define BB 4
#define LL 4096
#define HIDN 1024
#define HH 16
#define DD 64
#define DMM 128
#define CSZ 64
#define NCH 64
#define MM (BB*LL)
#define EPSF 1e-6f
#define NPROC ((size_t)BB*HH*LL*DD)
#define NGATE ((size_t)BB*HH*LL)

static __device__ float g_qkv [(size_t)3*MM*HIDN];
static __device__ float g_proc[(size_t)3*NPROC];
static __device__ float g_gate[(size_t)3*NGATE];
static __device__ float g_wt  [(size_t)64*64*132];
static __device__ __nv_bfloat16 g_Xhi[(size_t)MM*HIDN];
static __device__ __nv_bfloat16 g_Xlo[(size_t)MM*HIDN];
static __device__ __nv_bfloat16 g_Whi[(size_t)3*HIDN*HIDN];
static __device__ __nv_bfloat16 g_Wlo[(size_t)3*HIDN*HIDN];

__device__ __forceinline__ float sigmf(float x){ return __fdividef(1.0f, 1.0f + __expf(-x)); }

typedef unsigned long long ull;
#define FMA2(acc,a,b) asm("fma.rn.f32x2 %0,%1,%2,%0;" : "+l"(acc) : "l"(a), "l"(b))
__device__ __forceinline__ ull dup2(float a){ ull r; asm("mov.b64 %0,{%1,%1};" : "=l"(r) : "r"(__float_as_uint(a))); return r; }
__device__ __forceinline__ float2 unp(ull v){ uint32_t l,h; asm("mov.b64 {%0,%1},%2;" : "=r"(l),"=r"(h) : "l"(v)); return make_float2(__uint_as_float(l),__uint_as_float(h)); }
__device__ __forceinline__ uint32_t smem_u32(const void* p){
    uint32_t a; asm("{ .reg .u64 t; cvta.to.shared.u64 t, %1; cvt.u32.u64 %0, t; }" : "=r"(a) : "l"(p)); return a;
}
__device__ __forceinline__ float ld_peer(uint32_t laddr, uint32_t prank){
    uint32_t ra; float v;
    asm("mapa.shared::cluster.u32 %0,%1,%2;" : "=r"(ra) : "r"(laddr), "r"(prank));
    asm volatile("ld.shared::cluster.f32 %0,[%1];" : "=f"(v) : "r"(ra));
    return v;
}
__device__ __forceinline__ void ldsm4(uint32_t* r, uint32_t a){
    asm volatile("ldmatrix.sync.aligned.m8n8.x4.shared.b16 {%0,%1,%2,%3},[%4];"
        : "=r"(r[0]),"=r"(r[1]),"=r"(r[2]),"=r"(r[3]) : "r"(a));
}
__device__ __forceinline__ void ldsm2(uint32_t* r, uint32_t a){
    asm volatile("ldmatrix.sync.aligned.m8n8.x2.shared.b16 {%0,%1},[%2];"
        : "=r"(r[0]),"=r"(r[1]) : "r"(a));
}
__device__ __forceinline__ void mma16816(float* c, const uint32_t* a, const uint32_t* b){
    asm volatile("mma.sync.aligned.m16n8k16.row.col.f32.bf16.bf16.f32 "
        "{%0,%1,%2,%3},{%4,%5,%6,%7},{%8,%9},{%0,%1,%2,%3};"
        : "+f"(c[0]),"+f"(c[1]),"+f"(c[2]),"+f"(c[3])
        : "r"(a[0]),"r"(a[1]),"r"(a[2]),"r"(a[3]),"r"(b[0]),"r"(b[1]));
}
#define CPA(dst,src) asm volatile("cp.async.cg.shared.global [%0],[%1],16;" :: "r"(dst),"l"(src))
#define CPC() asm volatile("cp.async.commit_group;" ::: "memory")
#define CPW(n) asm volatile("cp.async.wait_group %0;" :: "n"(n) : "memory")

// ---------------- K0: fp32 -> bf16 hi/lo ----------------
__global__ void __launch_bounds__(256) k_split(const float* __restrict__ src,
    __nv_bfloat16* __restrict__ hi, __nv_bfloat16* __restrict__ lo, int n)
{
    int i = (blockIdx.x*256 + threadIdx.x)*4;
    if (i >= n) return;
    float4 v = *(const float4*)(src + i);
    float f[4] = {v.x,v.y,v.z,v.w};
    __nv_bfloat16 h[4], l[4];
#pragma unroll
    for (int j = 0; j < 4; j++){
        h[j] = __float2bfloat16_rn(f[j]);
        l[j] = __float2bfloat16_rn(f[j] - __bfloat162float(h[j]));
    }
    *(__nv_bfloat162*)(hi+i)   = __halves2bfloat162(h[0],h[1]);
    *(__nv_bfloat162*)(hi+i+2) = __halves2bfloat162(h[2],h[3]);
    *(__nv_bfloat162*)(lo+i)   = __halves2bfloat162(l[0],l[1]);
    *(__nv_bfloat162*)(lo+i+2) = __halves2bfloat162(l[2],l[3]);
}

// ---------------- K1: qkv GEMM, mma.sync bf16, 2 CTA/SM ----------------
#define STG_B 24576
#define QSMEM (4*STG_B)

__global__ void __launch_bounds__(256,2) k_qkv()
{
    extern __shared__ __align__(16) char qs[];
    const int t = threadIdx.x, wid = t>>5, lam = t&31;
    const int z = blockIdx.z, n0 = blockIdx.x*128, m0 = blockIdx.y*128;
    const uint32_t sb = smem_u32(qs);
    const int r = t>>1, q = t&1;
    const __nv_bfloat16* Ah = g_Xhi + (size_t)(m0+r)*HIDN + q*8;
    const __nv_bfloat16* Al = g_Xlo + (size_t)(m0+r)*HIDN + q*8;
    const __nv_bfloat16* Bh = g_Whi + (size_t)z*HIDN*HIDN + (size_t)(n0+r)*HIDN + q*8;
    const __nv_bfloat16* Bl = g_Wlo + (size_t)z*HIDN*HIDN + (size_t)(n0+r)*HIDN + q*8;
    const uint32_t soff = (uint32_t)(r*48 + q*16);

    float acc[4][4][4] = {};
    const int wm = (wid>>2)*64, wn = (wid&3)*32;
    const uint32_t a_l = (uint32_t)((lam & 15)*48 + (lam>>4)*16);
    const uint32_t b_l = (uint32_t)((lam & 7)*48 + ((lam>>3)&1)*16);

#define ISSUE(s_) do{ uint32_t ds = sb + (uint32_t)(((s_)&3)*STG_B) + soff; int k0 = (s_)*16; \
    CPA(ds,       Ah + k0); CPA(ds+6144,  Al + k0); \
    CPA(ds+12288, Bh + k0); CPA(ds+18432, Bl + k0); CPC(); }while(0)

    ISSUE(0); ISSUE(1); ISSUE(2);
    for (int s = 0; s < 64; s++){
        CPW(2);
        __syncthreads();
        if (s < 61) ISSUE(s+3); else CPC();
        uint32_t cb = sb + (uint32_t)((s&3)*STG_B);
        uint32_t bh4[4][2], bl4[4][2];
#pragma unroll
        for (int ni = 0; ni < 4; ni++){
            uint32_t rowb = cb + 12288 + (uint32_t)(wn + ni*8)*48 + b_l;
            ldsm2(bh4[ni], rowb); ldsm2(bl4[ni], rowb + 6144);
        }
#pragma unroll
        for (int mi = 0; mi < 4; mi++){
            uint32_t ah[4], al[4];
            uint32_t rowb = cb + (uint32_t)(wm + mi*16)*48 + a_l;
            ldsm4(ah, rowb); ldsm4(al, rowb + 6144);
#pragma unroll
            for (int ni = 0; ni < 4; ni++){
                mma16816(acc[mi][ni], ah, bh4[ni]);
                mma16816(acc[mi][ni], ah, bl4[ni]);
                mma16816(acc[mi][ni], al, bh4[ni]);
            }
        }
    }
#undef ISSUE
    float* C = g_qkv + (size_t)z*MM*HIDN;
    const int rr = lam>>2, cc2 = (lam&3)*2;
#pragma unroll
    for (int mi = 0; mi < 4; mi++){
        int row0 = m0 + wm + mi*16 + rr;
#pragma unroll
        for (int ni = 0; ni < 4; ni++){
            int col = n0 + wn + ni*8 + cc2;
            *(float2*)&C[(size_t)row0*HIDN + col]     = make_float2(acc[mi][ni][0], acc[mi][ni][1]);
            *(float2*)&C[(size_t)(row0+8)*HIDN + col] = make_float2(acc[mi][ni][2], acc[mi][ni][3]);
        }
    }
}

// ---------------- K2: gate projections ----------------
__global__ void __launch_bounds__(256) k_gate(
    const float* __restrict__ X,
    const float* __restrict__ mdw, const float* __restrict__ mdb,
    const float* __restrict__ sw,  const float* __restrict__ sb,
    const float* __restrict__ lw,  const float* __restrict__ lb)
{
    __shared__ float As[16][68];
    __shared__ float Bg[16][52];
    const int m0 = blockIdx.x * 64;
    const int t = threadIdx.x;
    const int lr = t >> 2, lk = (t & 3) * 4;
    const int ty = t >> 4, tx = t & 15;
    float acc[4][3] = {};
    const float* Arow = X + (size_t)(m0 + lr) * HIDN + lk;
    for (int k0 = 0; k0 < HIDN; k0 += 16){
        float4 av = *(const float4*)(Arow + k0);
        As[lk+0][lr]=av.x; As[lk+1][lr]=av.y; As[lk+2][lr]=av.z; As[lk+3][lr]=av.w;
        if (t < 192){
#pragma unroll
            for (int j = 0; j < 4; j++){
                int idx = t*4+j, n = idx>>4, k = idx&15;
                const float* wp = (n<16)?(mdw+(size_t)n*HIDN):(n<32)?(sw+(size_t)(n-16)*HIDN):(lw+(size_t)(n-32)*HIDN);
                Bg[k][n] = wp[k0+k];
            }
        }
        __syncthreads();
#pragma unroll
        for (int kk = 0; kk < 16; kk++){
            float4 a = *(const float4*)&As[kk][ty*4];
            float ar[4] = {a.x,a.y,a.z,a.w};
            float b0=Bg[kk][tx*3], b1=Bg[kk][tx*3+1], b2=Bg[kk][tx*3+2];
#pragma unroll
            for (int i = 0; i < 4; i++){ acc[i][0]+=ar[i]*b0; acc[i][1]+=ar[i]*b1; acc[i][2]+=ar[i]*b2; }
        }
        __syncthreads();
    }
#pragma unroll
    for (int i = 0; i < 4; i++)
#pragma unroll
        for (int j = 0; j < 3; j++){
            int m = m0 + ty*4 + i, o = tx*3 + j;
            float bias = (o<16)?mdb[o]:(o<32)?sb[o-16]:lb[o-32];
            float v = sigmf(acc[i][j] + bias);
            int bc = m >> 12, l = m & (LL-1), g = o >> 4, hh = o & 15;
            g_gate[(size_t)g*NGATE + ((size_t)(bc*HH+hh))*LL + l] = (g==0)?(1.0f-v):v;
        }
}

// ---------------- K2b: per-chunk gate suffix weights ----------------
__global__ void __launch_bounds__(64) k_wt()
{
    const int ch = blockIdx.x, bh = blockIdx.y, t = threadIdx.x;
    const float* md = g_gate + 0*NGATE + (size_t)bh*LL + ch*CSZ;
    const float* sd = g_gate + 1*NGATE + (size_t)bh*LL + ch*CSZ;
    __shared__ float m[64], s[64];
    m[t] = md[t]; s[t] = sd[t];
    __syncthreads();
    float wm = 1.0f, ws = 1.0f;
    for (int i = t+1; i < 64; i++){ wm *= m[i]; ws *= s[i]; }
    float* row = g_wt + (size_t)(bh*64+ch)*132;
    row[t] = wm; row[64+t] = ws;
    if (t == 0){ row[128] = wm*m[0]; row[129] = ws*s[0]; row[130]=0.0f; row[131]=0.0f; }
}

// ---------------- K3: causal conv + silu (+rmsnorm), 8 timesteps ----------------
#define CT 8
__global__ void __launch_bounds__(256) k_conv(
    const float* __restrict__ cqw, const float* __restrict__ cqb,
    const float* __restrict__ ckw, const float* __restrict__ ckb,
    const float* __restrict__ cvw, const float* __restrict__ cvb,
    const float* __restrict__ qnw, const float* __restrict__ knw)
{
    const int z = blockIdx.z, b = blockIdx.y, l0 = blockIdx.x*CT;
    const float* w    = (z==0)?cqw:(z==1)?ckw:cvw;
    const float* bias = (z==0)?cqb:(z==1)?ckb:cvb;
    const float* src = g_qkv + (size_t)z*MM*HIDN + (size_t)b*LL*HIDN;
    __shared__ float rows[CT+3][1024];
    __shared__ float hs[CT*16];
    const int t = threadIdx.x;
    if (t < CT*16) hs[t] = 0.0f;
    for (int e = t; e < (CT+3)*256; e += 256){
        int j = e>>8, c4 = (e&255)*4;
        int ls = l0 - 3 + j;
        float4 v = (ls >= 0) ? *(const float4*)(src + (size_t)ls*HIDN + c4) : make_float4(0,0,0,0);
        *(float4*)&rows[j][c4] = v;
    }
    __syncthreads();
    const int c0 = t*4, head = c0>>6, d0 = c0&63;
    float4 w0 = *(const float4*)&w[(c0+0)*4];
    float4 w1 = *(const float4*)&w[(c0+1)*4];
    float4 w2 = *(const float4*)&w[(c0+2)*4];
    float4 w3 = *(const float4*)&w[(c0+3)*4];
    float4 bz = *(const float4*)&bias[c0];
    float y[CT][4];
#pragma unroll
    for (int li = 0; li < CT; li++){
        float a0=bz.x, a1=bz.y, a2=bz.z, a3=bz.w;
#pragma unroll
        for (int k = 0; k < 4; k++){
            float4 x = *(const float4*)&rows[li + k][c0];
            a0 += ((const float*)&w0)[k]*x.x; a1 += ((const float*)&w1)[k]*x.y;
            a2 += ((const float*)&w2)[k]*x.z; a3 += ((const float*)&w3)[k]*x.w;
        }
        a0 *= sigmf(a0); a1 *= sigmf(a1); a2 *= sigmf(a2); a3 *= sigmf(a3);
        y[li][0]=a0; y[li][1]=a1; y[li][2]=a2; y[li][3]=a3;
        if (z < 2) atomicAdd(&hs[li*16+head], a0*a0+a1*a1+a2*a2+a3*a3);
    }
    __syncthreads();
#pragma unroll
    for (int li = 0; li < CT; li++){
        float4 o;
        if (z < 2){
            float sc = rsqrtf(hs[li*16+head]*(1.0f/64.0f) + EPSF);
            const float* nw = (z==0)?qnw:knw;
            o = make_float4(y[li][0]*sc*nw[d0], y[li][1]*sc*nw[d0+1], y[li][2]*sc*nw[d0+2], y[li][3]*sc*nw[d0+3]);
        } else {
            o = make_float4(y[li][0], y[li][1], y[li][2], y[li][3]);
        }
        *(float4*)(g_proc + (size_t)z*NPROC + (((size_t)(b*HH+head))*LL + l0+li)*DD + d0) = o;
    }
}

// ---------------- K4: cluster-2 chunked scan, prefetched ----------------
#define OW1 0
#define OW2 8448
#define OW2T 17152
#define OZ1 25600
#define OX1 29824
#define OG  34048
#define OKC 36224
#define OQC 40576
#define OPXM 44928
#define OPKM 46976
#define OPW1 47232
#define OPW2 49280
#define OEXC 50304
#define OLW 51072
#define OVV 51488
#define SCAN_BYTES ((OVV + 384)*4)

__global__ void __launch_bounds__(512,1) __cluster_dims__(2,1,1) k_scan(
    const float* __restrict__ W1g, const float* __restrict__ W2g, float* __restrict__ out)
{
    extern __shared__ float sm[];
    float* sW1  = sm + OW1;
    float* sW2  = sm + OW2;
    float* sW2T = sm + OW2T;
    float* sZ1  = sm + OZ1;   // [32][132]
    float* sX1  = sm + OX1;   // [32][132]
    float* sG   = sm + OG;    // [32][68]
    float* pXm  = sm + OPXM;  // [16][128]
    float* pKm  = sm + OPKM;  // [4][64]
    float* pW1  = sm + OPW1;  // [16][128]
    float* pW2  = sm + OPW2;  // [16][64]
    float* exch = sm + OEXC;  // [2][384]
    float* sW1s = sm + OVV;  float* sW2s = sW1s+128; float* sKm = sW2s+64; float* sXm = sKm+64;

    const int t = threadIdx.x;
    const int bh = blockIdx.x >> 1;
    const uint32_t rank = blockIdx.x & 1, prank = rank ^ 1;
    const int b = bh >> 4, h = bh & 15;
    const int ro = rank*32;
    const float* qp = g_proc + 0*NPROC + (size_t)bh*LL*DD;
    const float* kp = g_proc + 1*NPROC + (size_t)bh*LL*DD;
    const float* vp = g_proc + 2*NPROC + (size_t)bh*LL*DD;
    const float* glr = g_gate + 2*NGATE + (size_t)bh*LL;

    for (int e = t; e < DD*DMM; e += 512){ int d=e>>7, c=e&127; sW1[d*132+c] = W1g[(size_t)h*DD*DMM+e]; }
    for (int e = t; e < DMM*DD; e += 512){ int c=e>>6, d=e&63; float v=W2g[(size_t)h*DMM*DD+e]; sW2[c*68+d]=v; sW2T[d*132+c]=v; }
    if (t < 128){ sW1s[t]=0.0f; sXm[t]=0.0f; }
    if (t < 64){ sW2s[t]=0.0f; sKm[t]=0.0f; }

    const uint32_t kc_u = smem_u32(sm+OKC), qc_u = smem_u32(sm+OQC), lw_u = smem_u32(sm+OLW);
    const uint32_t exc_base = smem_u32(exch);
    const int pfi = t>>4, pfc = (t&15)*16;

#define PF(ch_) do{ int pn=(ch_)&1; int lb=(ch_)*CSZ+ro; \
    CPA(kc_u + pn*8704 + pfi*272 + pfc, kp + (size_t)(lb+pfi)*DD + (pfc>>2)); \
    CPA(qc_u + pn*8704 + pfi*272 + pfc, qp + (size_t)(lb+pfi)*DD + (pfc>>2)); \
    if (t < 16) CPA(lw_u + pn*832 + t*16, glr + (size_t)(ch_)*CSZ + t*4); \
    if (t < 33) CPA(lw_u + pn*832 + 256 + t*16, g_wt + (size_t)(bh*64+(ch_))*132 + t*4); \
    CPC(); }while(0)

    PF(0);
    CPW(0);
    __syncthreads();

    const int rg = t>>5;
    const int r0 = rg*2;
    const int c0 = (t&31)*4;
    const int c2 = (t&31)*2;

    for (int ch = 0; ch < NCH; ch++){
        const int l0 = ch*CSZ;
        const int par = ch & 1;
        float* kcb = sm + OKC + par*2176;
        float* qcb = sm + OQC + par*2176;
        float* lw  = sm + OLW + par*208;
        float* sLr = lw; float* sWt = lw+64; float* sWs = lw+128;

        float vcr[2][2];
#pragma unroll
        for (int i = 0; i < 2; i++){
            float2 vv = *(const float2*)(vp + (size_t)(l0+ro+r0+i)*DD + c2);
            vcr[i][0]=vv.x; vcr[i][1]=vv.y;
        }

        // ---- B: Z1 = kc@W1, X1 = silu; fold pXm; pKm fold ----
        {
            ull acc[2][2] = {};
            for (int d = 0; d < DD; d += 2){
                float2 a0 = *(const float2*)&kcb[r0*68+d];
                float2 a1 = *(const float2*)&kcb[(r0+1)*68+d];
                ulonglong2 b0 = *(const ulonglong2*)&sW1[d*132+c0];
                ulonglong2 b1 = *(const ulonglong2*)&sW1[(d+1)*132+c0];
                FMA2(acc[0][0],dup2(a0.x),b0.x); FMA2(acc[0][1],dup2(a0.x),b0.y);
                FMA2(acc[1][0],dup2(a1.x),b0.x); FMA2(acc[1][1],dup2(a1.x),b0.y);
                FMA2(acc[0][0],dup2(a0.y),b1.x); FMA2(acc[0][1],dup2(a0.y),b1.y);
                FMA2(acc[1][0],dup2(a1.y),b1.x); FMA2(acc[1][1],dup2(a1.y),b1.y);
            }
            float px[4] = {0,0,0,0};
#pragma unroll
            for (int i = 0; i < 2; i++){
                float2 p = unp(acc[i][0]), qq = unp(acc[i][1]);
                float xv[4] = {p.x*sigmf(p.x), p.y*sigmf(p.y), qq.x*sigmf(qq.x), qq.y*sigmf(qq.y)};
                *(float4*)&sZ1[(r0+i)*132+c0] = make_float4(p.x,p.y,qq.x,qq.y);
                *(float4*)&sX1[(r0+i)*132+c0] = make_float4(xv[0],xv[1],xv[2],xv[3]);
                float wv = sWt[ro+r0+i];
#pragma unroll
                for (int j = 0; j < 4; j++) px[j] += wv*xv[j];
            }
            *(float4*)&pXm[rg*128+c0] = make_float4(px[0],px[1],px[2],px[3]);
            if (t < 256){
                int i0 = (t>>6)*8, dd = t&63;
                float s = 0.0f;
#pragma unroll
                for (int j = 0; j < 8; j++) s += sWt[ro+i0+j]*kcb[(i0+j)*68+dd];
                pKm[(t>>6)*64+dd] = s;
            }
        }
        __syncwarp();

        // ---- C: g0 = X1@W2 - vc -> sG; fold pW2 ----
        {
            ull acc[2] = {};
            for (int cc = 0; cc < DMM; cc += 4){
                float4 a0 = *(const float4*)&sX1[(r0+0)*132+cc];
                float4 a1 = *(const float4*)&sX1[(r0+1)*132+cc];
#pragma unroll
                for (int u = 0; u < 4; u++){
                    ull bv = *(const ull*)&sW2[(cc+u)*68+c2];
                    float e0 = u==0?a0.x:u==1?a0.y:u==2?a0.z:a0.w;
                    float e1 = u==0?a1.x:u==1?a1.y:u==2?a1.z:a1.w;
                    FMA2(acc[0],dup2(e0),bv); FMA2(acc[1],dup2(e1),bv);
                }
            }
            float pw[2] = {0,0};
#pragma unroll
            for (int i = 0; i < 2; i++){
                float2 p = unp(acc[i]);
                float g0 = p.x - vcr[i][0], g1 = p.y - vcr[i][1];
                *(float2*)&sG[(r0+i)*68+c2] = make_float2(g0, g1);
                float wl = sWs[ro+r0+i] * (-sLr[ro+r0+i]);
                pw[0] += wl*g0; pw[1] += wl*g1;
            }
            *(float2*)&pW2[rg*64+c2] = make_float2(pw[0], pw[1]);
        }
        __syncwarp();

        // ---- E: gZ1 = -lr*(g0@W2^T)*silu_bwd(Z1); fold pW1 ----
        {
            ull acc[2][2] = {};
            for (int d = 0; d < DD; d++){
                ull a0 = dup2(sG[(r0+0)*68+d]), a1 = dup2(sG[(r0+1)*68+d]);
                ulonglong2 bv = *(const ulonglong2*)&sW2T[d*132+c0];
                FMA2(acc[0][0],a0,bv.x); FMA2(acc[0][1],a0,bv.y);
                FMA2(acc[1][0],a1,bv.x); FMA2(acc[1][1],a1,bv.y);
            }
            float pw[4] = {0,0,0,0};
#pragma unroll
            for (int i = 0; i < 2; i++){
                float nlr = -sLr[ro+r0+i];
                float ws = sWs[ro+r0+i];
                float2 p = unp(acc[i][0]), qq = unp(acc[i][1]);
                float g[4] = {p.x,p.y,qq.x,qq.y};
#pragma unroll
                for (int j = 0; j < 4; j++){
                    float z = sZ1[(r0+i)*132+c0+j];
                    float sg = sigmf(z);
                    pw[j] += ws * (nlr*g[j]*(sg*(1.0f + z*(1.0f - sg))));
                }
            }
            *(float4*)&pW1[rg*128+c0] = make_float4(pw[0],pw[1],pw[2],pw[3]);
        }
        __syncthreads();

        // ---- R1: local reduce -> exch ----
        if (t < 384){
            float s = 0.0f;
            if (t < 128){
#pragma unroll
                for (int g = 0; g < 16; g++) s += pXm[g*128+t];
            } else if (t < 192){
                int d = t-128;
#pragma unroll
                for (int g = 0; g < 4; g++) s += pKm[g*64+d];
            } else if (t < 320){
                int c = t-192;
#pragma unroll
                for (int g = 0; g < 16; g++) s += pW1[g*128+c];
            } else {
                int d = t-320;
#pragma unroll
                for (int g = 0; g < 16; g++) s += pW2[g*64+d];
            }
            exch[par*384 + t] = s;
        }
        asm volatile("barrier.cluster.arrive.aligned;" ::: "memory");
        asm volatile("barrier.cluster.wait.aligned;" ::: "memory");

        // ---- R2: cross-CTA sum, update carries ----
        if (t < 384){
            float ov = exch[par*384 + t];
            float pv = ld_peer(exc_base + (uint32_t)(par*384 + t)*4u, prank);
            float v0 = (rank == 0) ? ov : pv;
            float v1 = (rank == 0) ? pv : ov;
            float total = v0 + v1;
            float m0 = lw[192], m1 = lw[193];
            if (t < 128)       sXm[t]      = m0*sXm[t]      + total;
            else if (t < 192)  sKm[t-128]  = m0*sKm[t-128]  + total;
            else if (t < 320)  sW1s[t-192] = m1*sW1s[t-192] + total;
            else               sW2s[t-320] = m1*sW2s[t-320] + total;
        }
        __syncthreads();

        // ---- G2: prefetch next chunk; W updates ----
        {
            if (ch+1 < NCH) PF(ch+1);
            float mp = lw[192];
            for (int e = t; e < DD*DMM; e += 512){
                int d = e>>7, c = e&127;
                sW1[d*132+c] = mp*sW1[d*132+c] + sKm[d]*sW1s[c];
            }
            for (int e = t; e < DMM*DD; e += 512){
                int c = e>>6, d = e&63;
                float v = mp*sW2[c*68+d] + sXm[c]*sW2s[d];
                sW2[c*68+d] = v; sW2T[d*132+c] = v;
            }
        }
        __syncthreads();

        // ---- H: Zq = qc@W1n ; silu -> sZ1 ----
        {
            ull acc[2][2] = {};
            for (int d = 0; d < DD; d += 2){
                float2 a0 = *(const float2*)&qcb[r0*68+d];
                float2 a1 = *(const float2*)&qcb[(r0+1)*68+d];
                ulonglong2 b0 = *(const ulonglong2*)&sW1[d*132+c0];
                ulonglong2 b1 = *(const ulonglong2*)&sW1[(d+1)*132+c0];
                FMA2(acc[0][0],dup2(a0.x),b0.x); FMA2(acc[0][1],dup2(a0.x),b0.y);
                FMA2(acc[1][0],dup2(a1.x),b0.x); FMA2(acc[1][1],dup2(a1.x),b0.y);
                FMA2(acc[0][0],dup2(a0.y),b1.x); FMA2(acc[0][1],dup2(a0.y),b1.y);
                FMA2(acc[1][0],dup2(a1.y),b1.x); FMA2(acc[1][1],dup2(a1.y),b1.y);
            }
#pragma unroll
            for (int i = 0; i < 2; i++){
                float2 p = unp(acc[i][0]), qq = unp(acc[i][1]);
                *(float4*)&sZ1[(r0+i)*132+c0] =
                    make_float4(p.x*sigmf(p.x), p.y*sigmf(p.y), qq.x*sigmf(qq.x), qq.y*sigmf(qq.y));
            }
        }
        __syncwarp();

        // ---- I: y = silu(Zq)@W2n -> sG ----
        {
            ull acc[2] = {};
            for (int cc = 0; cc < DMM; cc += 4){
                float4 a0 = *(const float4*)&sZ1[(r0+0)*132+cc];
                float4 a1 = *(const float4*)&sZ1[(r0+1)*132+cc];
#pragma unroll
                for (int u = 0; u < 4; u++){
                    ull bv = *(const ull*)&sW2[(cc+u)*68+c2];
                    float e0 = u==0?a0.x:u==1?a0.y:u==2?a0.z:a0.w;
                    float e1 = u==0?a1.x:u==1?a1.y:u==2?a1.z:a1.w;
                    FMA2(acc[0],dup2(e0),bv); FMA2(acc[1],dup2(e1),bv);
                }
            }
#pragma unroll
            for (int i = 0; i < 2; i++){
                float2 p = unp(acc[i]);
                *(float2*)&sG[(r0+i)*68+c2] = make_float2(p.x, p.y);
            }
        }
        __syncthreads();

        // ---- store own rows ----
        for (int e = t; e < 32*64; e += 512){
            int d = e>>5, i = e&31;
            out[(size_t)b*LL*HIDN + ((size_t)(h*DD+d))*LL + (l0+ro+i)] = sG[i*68+d];
        }
        CPW(0);
        __syncthreads();
    }
#undef PF
}

// ---------------- launch ----------------
extern "C" void kernel_launch(void* const* d_in, const int* in_sizes, int n_in,
                              void* d_out, int out_size) {
    (void)in_sizes; (void)n_in; (void)out_size;
    const float* X   = (const float*)d_in[0];
    const float* Wq  = (const float*)d_in[1];
    const float* Wk  = (const float*)d_in[2];
    const float* Wv  = (const float*)d_in[3];
    const float* cqw = (const float*)d_in[4];
    const float* cqb = (const float*)d_in[5];
    const float* ckw = (const float*)d_in[6];
    const float* ckb = (const float*)d_in[7];
    const float* cvw = (const float*)d_in[8];
    const float* cvb = (const float*)d_in[9];
    const float* qnw = (const float*)d_in[10];
    const float* knw = (const float*)d_in[11];
    const float* mdw = (const float*)d_in[12];
    const float* mdb = (const float*)d_in[13];
    const float* sw  = (const float*)d_in[14];
    const float* sb  = (const float*)d_in[15];
    const float* lw  = (const float*)d_in[16];
    const float* lb  = (const float*)d_in[17];
    const float* W1g = (const float*)d_in[18];
    const float* W2g = (const float*)d_in[19];
    float* out = (float*)d_out;

    cudaFuncSetAttribute(k_qkv, cudaFuncAttributeMaxDynamicSharedMemorySize, QSMEM);
    cudaFuncSetAttribute(k_scan, cudaFuncAttributeMaxDynamicSharedMemorySize, SCAN_BYTES);

    __nv_bfloat16 *xhi, *xlo, *whi, *wlo;
    cudaGetSymbolAddress((void**)&xhi, g_Xhi);
    cudaGetSymbolAddress((void**)&xlo, g_Xlo);
    cudaGetSymbolAddress((void**)&whi, g_Whi);
    cudaGetSymbolAddress((void**)&wlo, g_Wlo);

    k_split<<<MM*HIDN/1024, 256>>>(X, xhi, xlo, MM*HIDN);
    k_split<<<HIDN*HIDN/1024, 256>>>(Wq, whi, wlo, HIDN*HIDN);
    k_split<<<HIDN*HIDN/1024, 256>>>(Wk, whi + (size_t)HIDN*HIDN, wlo + (size_t)HIDN*HIDN, HIDN*HIDN);
    k_split<<<HIDN*HIDN/1024, 256>>>(Wv, whi + (size_t)2*HIDN*HIDN, wlo + (size_t)2*HIDN*HIDN, HIDN*HIDN);
    k_qkv<<<dim3(HIDN/128, MM/128, 3), 256, QSMEM>>>();
    k_gate<<<dim3(MM/64), 256>>>(X, mdw, mdb, sw, sb, lw, lb);
    k_wt<<<dim3(NCH, BB*HH), 64>>>();
    k_conv<<<dim3(LL/CT, BB, 3), 256>>>(cqw, cqb, ckw, ckb, cvw, cvb, qnw, knw);
    k_scan<<<dim3(BB*HH*2), 512, SCAN_BYTES>>>(W1g, W2g, out);
}

// round 8
// speedup vs baseline: 2.9133x; 1.1250x over previous
#include <cuda_runtime.h>
#include <cuda_fp16.h>
#include <math.h>
#include <stdint.h>

#define BB 4
#define LL 4096
#define HIDN 1024
#define HH 16
#define DD 64
#define DMM 128
#define CSZ 64
#define NCH 64
#define MM (BB*LL)
#define EPSF 1e-6f
#define NPROC ((size_t)BB*HH*LL*DD)
#define NGATE ((size_t)BB*HH*LL)

static __device__ float g_qkv [(size_t)3*MM*HIDN];
static __device__ float g_proc[(size_t)3*NPROC];
static __device__ float g_gate[(size_t)3*NGATE];
static __device__ float g_wt  [(size_t)64*64*132];
static __device__ __half g_Xhi[(size_t)MM*HIDN];
static __device__ __half g_Xlo[(size_t)MM*HIDN];
static __device__ __half g_Whi[(size_t)3*HIDN*HIDN];

__device__ __forceinline__ float sigmf(float x){ return __fdividef(1.0f, 1.0f + __expf(-x)); }

typedef unsigned long long ull;
#define FMA2(acc,a,b) asm("fma.rn.f32x2 %0,%1,%2,%0;" : "+l"(acc) : "l"(a), "l"(b))
__device__ __forceinline__ ull dup2(float a){ ull r; asm("mov.b64 %0,{%1,%1};" : "=l"(r) : "r"(__float_as_uint(a))); return r; }
__device__ __forceinline__ float2 unp(ull v){ uint32_t l,h; asm("mov.b64 {%0,%1},%2;" : "=r"(l),"=r"(h) : "l"(v)); return make_float2(__uint_as_float(l),__uint_as_float(h)); }
__device__ __forceinline__ uint32_t smem_u32(const void* p){
    uint32_t a; asm("{ .reg .u64 t; cvta.to.shared.u64 t, %1; cvt.u32.u64 %0, t; }" : "=r"(a) : "l"(p)); return a;
}
__device__ __forceinline__ float ld_peer(uint32_t laddr, uint32_t prank){
    uint32_t ra; float v;
    asm("mapa.shared::cluster.u32 %0,%1,%2;" : "=r"(ra) : "r"(laddr), "r"(prank));
    asm volatile("ld.shared::cluster.f32 %0,[%1];" : "=f"(v) : "r"(ra));
    return v;
}
__device__ __forceinline__ void ldsm4(uint32_t* r, uint32_t a){
    asm volatile("ldmatrix.sync.aligned.m8n8.x4.shared.b16 {%0,%1,%2,%3},[%4];"
        : "=r"(r[0]),"=r"(r[1]),"=r"(r[2]),"=r"(r[3]) : "r"(a));
}
__device__ __forceinline__ void ldsm2(uint32_t* r, uint32_t a){
    asm volatile("ldmatrix.sync.aligned.m8n8.x2.shared.b16 {%0,%1},[%2];"
        : "=r"(r[0]),"=r"(r[1]) : "r"(a));
}
__device__ __forceinline__ void mma16816(float* c, const uint32_t* a, const uint32_t* b){
    asm volatile("mma.sync.aligned.m16n8k16.row.col.f32.f16.f16.f32 "
        "{%0,%1,%2,%3},{%4,%5,%6,%7},{%8,%9},{%0,%1,%2,%3};"
        : "+f"(c[0]),"+f"(c[1]),"+f"(c[2]),"+f"(c[3])
        : "r"(a[0]),"r"(a[1]),"r"(a[2]),"r"(a[3]),"r"(b[0]),"r"(b[1]));
}
#define CPA(dst,src) asm volatile("cp.async.cg.shared.global [%0],[%1],16;" :: "r"(dst),"l"(src))
#define CPC() asm volatile("cp.async.commit_group;" ::: "memory")
#define CPW(n) asm volatile("cp.async.wait_group %0;" :: "n"(n) : "memory")

// ---------------- K0a: X -> fp16 hi+lo ----------------
__global__ void __launch_bounds__(256) k_splitA(const float* __restrict__ src,
    __half* __restrict__ hi, __half* __restrict__ lo, int n)
{
    int i = (blockIdx.x*256 + threadIdx.x)*4;
    if (i >= n) return;
    float4 v = *(const float4*)(src + i);
    float f[4] = {v.x,v.y,v.z,v.w};
    __half h[4], l[4];
#pragma unroll
    for (int j = 0; j < 4; j++){
        h[j] = __float2half_rn(f[j]);
        l[j] = __float2half_rn(f[j] - __half2float(h[j]));
    }
    *(__half2*)(hi+i)   = __halves2half2(h[0],h[1]);
    *(__half2*)(hi+i+2) = __halves2half2(h[2],h[3]);
    *(__half2*)(lo+i)   = __halves2half2(l[0],l[1]);
    *(__half2*)(lo+i+2) = __halves2half2(l[2],l[3]);
}
// ---------------- K0b: W -> fp16 hi only ----------------
__global__ void __launch_bounds__(256) k_cvtW(const float* __restrict__ src,
    __half* __restrict__ hi, int n)
{
    int i = (blockIdx.x*256 + threadIdx.x)*4;
    if (i >= n) return;
    float4 v = *(const float4*)(src + i);
    *(__half2*)(hi+i)   = __halves2half2(__float2half_rn(v.x), __float2half_rn(v.y));
    *(__half2*)(hi+i+2) = __halves2half2(__float2half_rn(v.z), __float2half_rn(v.w));
}

// ---------------- K1: qkv GEMM, fp16 2-term, cp.async 4-stage, 2 CTA/SM ----------------
#define STG_B 18432
#define QSMEM (4*STG_B)

__global__ void __launch_bounds__(256,2) k_qkv()
{
    extern __shared__ __align__(16) char qs[];
    const int t = threadIdx.x, wid = t>>5, lam = t&31;
    const int z = blockIdx.z, n0 = blockIdx.x*128, m0 = blockIdx.y*128;
    const uint32_t sb = smem_u32(qs);
    const int r = t>>1, q = t&1;
    const __half* Ah = g_Xhi + (size_t)(m0+r)*HIDN + q*8;
    const __half* Al = g_Xlo + (size_t)(m0+r)*HIDN + q*8;
    const __half* Bh = g_Whi + (size_t)z*HIDN*HIDN + (size_t)(n0+r)*HIDN + q*8;
    const uint32_t soff = (uint32_t)(r*48 + q*16);

    float acc[4][4][4] = {};
    const int wm = (wid>>2)*64, wn = (wid&3)*32;
    const uint32_t a_l = (uint32_t)((lam & 15)*48 + (lam>>4)*16);
    const uint32_t b_l = (uint32_t)((lam & 7)*48 + ((lam>>3)&1)*16);

#define ISSUE(s_) do{ uint32_t ds = sb + (uint32_t)(((s_)&3)*STG_B) + soff; int k0 = (s_)*16; \
    CPA(ds,       Ah + k0); CPA(ds+6144,  Al + k0); CPA(ds+12288, Bh + k0); CPC(); }while(0)

    ISSUE(0); ISSUE(1); ISSUE(2);
    for (int s = 0; s < 64; s++){
        CPW(2);
        __syncthreads();
        if (s < 61) ISSUE(s+3); else CPC();
        uint32_t cb = sb + (uint32_t)((s&3)*STG_B);
        uint32_t bh4[4][2];
#pragma unroll
        for (int ni = 0; ni < 4; ni++){
            ldsm2(bh4[ni], cb + 12288 + (uint32_t)(wn + ni*8)*48 + b_l);
        }
#pragma unroll
        for (int mi = 0; mi < 4; mi++){
            uint32_t ah[4], al[4];
            uint32_t rowb = cb + (uint32_t)(wm + mi*16)*48 + a_l;
            ldsm4(ah, rowb); ldsm4(al, rowb + 6144);
#pragma unroll
            for (int ni = 0; ni < 4; ni++){
                mma16816(acc[mi][ni], ah, bh4[ni]);
                mma16816(acc[mi][ni], al, bh4[ni]);
            }
        }
    }
#undef ISSUE
    float* C = g_qkv + (size_t)z*MM*HIDN;
    const int rr = lam>>2, cc2 = (lam&3)*2;
#pragma unroll
    for (int mi = 0; mi < 4; mi++){
        int row0 = m0 + wm + mi*16 + rr;
#pragma unroll
        for (int ni = 0; ni < 4; ni++){
            int col = n0 + wn + ni*8 + cc2;
            *(float2*)&C[(size_t)row0*HIDN + col]     = make_float2(acc[mi][ni][0], acc[mi][ni][1]);
            *(float2*)&C[(size_t)(row0+8)*HIDN + col] = make_float2(acc[mi][ni][2], acc[mi][ni][3]);
        }
    }
}

// ---------------- K2: gate projections + fused suffix weights ----------------
__global__ void __launch_bounds__(256) k_gate(
    const float* __restrict__ X,
    const float* __restrict__ mdw, const float* __restrict__ mdb,
    const float* __restrict__ sw,  const float* __restrict__ sb,
    const float* __restrict__ lw,  const float* __restrict__ lb)
{
    __shared__ float As[16][68];
    __shared__ float Bg[16][52];
    __shared__ float gv[32][68];   // [(h,g)][l] gate values for suffix pass
    const int m0 = blockIdx.x * 64;
    const int t = threadIdx.x;
    const int lr = t >> 2, lk = (t & 3) * 4;
    const int ty = t >> 4, tx = t & 15;
    float acc[4][3] = {};
    const float* Arow = X + (size_t)(m0 + lr) * HIDN + lk;
    for (int k0 = 0; k0 < HIDN; k0 += 16){
        float4 av = *(const float4*)(Arow + k0);
        As[lk+0][lr]=av.x; As[lk+1][lr]=av.y; As[lk+2][lr]=av.z; As[lk+3][lr]=av.w;
        if (t < 192){
#pragma unroll
            for (int j = 0; j < 4; j++){
                int idx = t*4+j, n = idx>>4, k = idx&15;
                const float* wp = (n<16)?(mdw+(size_t)n*HIDN):(n<32)?(sw+(size_t)(n-16)*HIDN):(lw+(size_t)(n-32)*HIDN);
                Bg[k][n] = wp[k0+k];
            }
        }
        __syncthreads();
#pragma unroll
        for (int kk = 0; kk < 16; kk++){
            float4 a = *(const float4*)&As[kk][ty*4];
            float ar[4] = {a.x,a.y,a.z,a.w};
            float b0=Bg[kk][tx*3], b1=Bg[kk][tx*3+1], b2=Bg[kk][tx*3+2];
#pragma unroll
            for (int i = 0; i < 4; i++){ acc[i][0]+=ar[i]*b0; acc[i][1]+=ar[i]*b1; acc[i][2]+=ar[i]*b2; }
        }
        __syncthreads();
    }
    const int b = m0 >> 12, l0 = m0 & (LL-1);
#pragma unroll
    for (int i = 0; i < 4; i++)
#pragma unroll
        for (int j = 0; j < 3; j++){
            int li = ty*4 + i, o = tx*3 + j;
            float bias = (o<16)?mdb[o]:(o<32)?sb[o-16]:lb[o-32];
            float v = sigmf(acc[i][j] + bias);
            int g = o >> 4, hh = o & 15;
            float gvv = (g==0)?(1.0f-v):v;
            g_gate[(size_t)g*NGATE + ((size_t)(b*HH+hh))*LL + l0 + li] = gvv;
            if (g < 2) gv[g*16+hh][li] = gvv;
        }
    __syncthreads();
    // suffix weights: thread t<32 handles (h = t&15, g = t>>4)
    if (t < 32){
        int hh = t & 15, g = t >> 4;
        int ch = l0 >> 6;
        float* row = g_wt + (size_t)(((b*HH+hh)*64) + ch)*132;
        float wv = 1.0f;
        row[g*64 + 63] = 1.0f;
        for (int j = 62; j >= 0; j--){ wv *= gv[t][j+1]; row[g*64 + j] = wv; }
        row[128+g] = wv * gv[t][0];
        if (g == 0){ row[130] = 0.0f; row[131] = 0.0f; }
    }
}

// ---------------- K3: causal conv + silu (+rmsnorm), 8 timesteps ----------------
#define CT 8
__global__ void __launch_bounds__(256) k_conv(
    const float* __restrict__ cqw, const float* __restrict__ cqb,
    const float* __restrict__ ckw, const float* __restrict__ ckb,
    const float* __restrict__ cvw, const float* __restrict__ cvb,
    const float* __restrict__ qnw, const float* __restrict__ knw)
{
    const int z = blockIdx.z, b = blockIdx.y, l0 = blockIdx.x*CT;
    const float* w    = (z==0)?cqw:(z==1)?ckw:cvw;
    const float* bias = (z==0)?cqb:(z==1)?ckb:cvb;
    const float* src = g_qkv + (size_t)z*MM*HIDN + (size_t)b*LL*HIDN;
    __shared__ float rows[CT+3][1024];
    __shared__ float hs[CT*16];
    const int t = threadIdx.x;
    if (t < CT*16) hs[t] = 0.0f;
    for (int e = t; e < (CT+3)*256; e += 256){
        int j = e>>8, c4 = (e&255)*4;
        int ls = l0 - 3 + j;
        float4 v = (ls >= 0) ? *(const float4*)(src + (size_t)ls*HIDN + c4) : make_float4(0,0,0,0);
        *(float4*)&rows[j][c4] = v;
    }
    __syncthreads();
    const int c0 = t*4, head = c0>>6, d0 = c0&63;
    float4 w0 = *(const float4*)&w[(c0+0)*4];
    float4 w1 = *(const float4*)&w[(c0+1)*4];
    float4 w2 = *(const float4*)&w[(c0+2)*4];
    float4 w3 = *(const float4*)&w[(c0+3)*4];
    float4 bz = *(const float4*)&bias[c0];
    float y[CT][4];
#pragma unroll
    for (int li = 0; li < CT; li++){
        float a0=bz.x, a1=bz.y, a2=bz.z, a3=bz.w;
#pragma unroll
        for (int k = 0; k < 4; k++){
            float4 x = *(const float4*)&rows[li + k][c0];
            a0 += ((const float*)&w0)[k]*x.x; a1 += ((const float*)&w1)[k]*x.y;
            a2 += ((const float*)&w2)[k]*x.z; a3 += ((const float*)&w3)[k]*x.w;
        }
        a0 *= sigmf(a0); a1 *= sigmf(a1); a2 *= sigmf(a2); a3 *= sigmf(a3);
        y[li][0]=a0; y[li][1]=a1; y[li][2]=a2; y[li][3]=a3;
        if (z < 2) atomicAdd(&hs[li*16+head], a0*a0+a1*a1+a2*a2+a3*a3);
    }
    __syncthreads();
#pragma unroll
    for (int li = 0; li < CT; li++){
        float4 o;
        if (z < 2){
            float sc = rsqrtf(hs[li*16+head]*(1.0f/64.0f) + EPSF);
            const float* nw = (z==0)?qnw:knw;
            o = make_float4(y[li][0]*sc*nw[d0], y[li][1]*sc*nw[d0+1], y[li][2]*sc*nw[d0+2], y[li][3]*sc*nw[d0+3]);
        } else {
            o = make_float4(y[li][0], y[li][1], y[li][2], y[li][3]);
        }
        *(float4*)(g_proc + (size_t)z*NPROC + (((size_t)(b*HH+head))*LL + l0+li)*DD + d0) = o;
    }
}

// ---------------- K4: cluster-2 chunked scan, prefetched ----------------
#define OW1 0
#define OW2 8448
#define OW2T 17152
#define OZ1 25600
#define OX1 29824
#define OG  34048
#define OKC 36224
#define OQC 40576
#define OPXM 44928
#define OPKM 46976
#define OPW1 47232
#define OPW2 49280
#define OEXC 50304
#define OLW 51072
#define OVV 51488
#define SCAN_BYTES ((OVV + 384)*4)

__global__ void __launch_bounds__(512,1) __cluster_dims__(2,1,1) k_scan(
    const float* __restrict__ W1g, const float* __restrict__ W2g, float* __restrict__ out)
{
    extern __shared__ float sm[];
    float* sW1  = sm + OW1;
    float* sW2  = sm + OW2;
    float* sW2T = sm + OW2T;
    float* sZ1  = sm + OZ1;
    float* sX1  = sm + OX1;
    float* sG   = sm + OG;
    float* pXm  = sm + OPXM;
    float* pKm  = sm + OPKM;
    float* pW1  = sm + OPW1;
    float* pW2  = sm + OPW2;
    float* exch = sm + OEXC;
    float* sW1s = sm + OVV;  float* sW2s = sW1s+128; float* sKm = sW2s+64; float* sXm = sKm+64;

    const int t = threadIdx.x;
    const int bh = blockIdx.x >> 1;
    const uint32_t rank = blockIdx.x & 1, prank = rank ^ 1;
    const int b = bh >> 4, h = bh & 15;
    const int ro = rank*32;
    const float* qp = g_proc + 0*NPROC + (size_t)bh*LL*DD;
    const float* kp = g_proc + 1*NPROC + (size_t)bh*LL*DD;
    const float* vp = g_proc + 2*NPROC + (size_t)bh*LL*DD;
    const float* glr = g_gate + 2*NGATE + (size_t)bh*LL;

    for (int e = t; e < DD*DMM; e += 512){ int d=e>>7, c=e&127; sW1[d*132+c] = W1g[(size_t)h*DD*DMM+e]; }
    for (int e = t; e < DMM*DD; e += 512){ int c=e>>6, d=e&63; float v=W2g[(size_t)h*DMM*DD+e]; sW2[c*68+d]=v; sW2T[d*132+c]=v; }
    if (t < 128){ sW1s[t]=0.0f; sXm[t]=0.0f; }
    if (t < 64){ sW2s[t]=0.0f; sKm[t]=0.0f; }

    const uint32_t kc_u = smem_u32(sm+OKC), qc_u = smem_u32(sm+OQC), lw_u = smem_u32(sm+OLW);
    const uint32_t exc_base = smem_u32(exch);
    const int pfi = t>>4, pfc = (t&15)*16;

#define PF(ch_) do{ int pn=(ch_)&1; int lb=(ch_)*CSZ+ro; \
    CPA(kc_u + pn*8704 + pfi*272 + pfc, kp + (size_t)(lb+pfi)*DD + (pfc>>2)); \
    CPA(qc_u + pn*8704 + pfi*272 + pfc, qp + (size_t)(lb+pfi)*DD + (pfc>>2)); \
    if (t < 16) CPA(lw_u + pn*832 + t*16, glr + (size_t)(ch_)*CSZ + t*4); \
    if (t < 33) CPA(lw_u + pn*832 + 256 + t*16, g_wt + (size_t)(bh*64+(ch_))*132 + t*4); \
    CPC(); }while(0)

    PF(0);
    CPW(0);
    __syncthreads();

    const int rg = t>>5;
    const int r0 = rg*2;
    const int c0 = (t&31)*4;
    const int c2 = (t&31)*2;

    for (int ch = 0; ch < NCH; ch++){
        const int l0 = ch*CSZ;
        const int par = ch & 1;
        float* kcb = sm + OKC + par*2176;
        float* qcb = sm + OQC + par*2176;
        float* lw  = sm + OLW + par*208;
        float* sLr = lw; float* sWt = lw+64; float* sWs = lw+128;

        float vcr[2][2];
#pragma unroll
        for (int i = 0; i < 2; i++){
            float2 vv = *(const float2*)(vp + (size_t)(l0+ro+r0+i)*DD + c2);
            vcr[i][0]=vv.x; vcr[i][1]=vv.y;
        }

        // ---- B: Z1 = kc@W1, X1 = silu; folds ----
        {
            ull acc[2][2] = {};
            for (int d = 0; d < DD; d += 2){
                float2 a0 = *(const float2*)&kcb[r0*68+d];
                float2 a1 = *(const float2*)&kcb[(r0+1)*68+d];
                ulonglong2 b0 = *(const ulonglong2*)&sW1[d*132+c0];
                ulonglong2 b1 = *(const ulonglong2*)&sW1[(d+1)*132+c0];
                FMA2(acc[0][0],dup2(a0.x),b0.x); FMA2(acc[0][1],dup2(a0.x),b0.y);
                FMA2(acc[1][0],dup2(a1.x),b0.x); FMA2(acc[1][1],dup2(a1.x),b0.y);
                FMA2(acc[0][0],dup2(a0.y),b1.x); FMA2(acc[0][1],dup2(a0.y),b1.y);
                FMA2(acc[1][0],dup2(a1.y),b1.x); FMA2(acc[1][1],dup2(a1.y),b1.y);
            }
            float px[4] = {0,0,0,0};
#pragma unroll
            for (int i = 0; i < 2; i++){
                float2 p = unp(acc[i][0]), qq = unp(acc[i][1]);
                float xv[4] = {p.x*sigmf(p.x), p.y*sigmf(p.y), qq.x*sigmf(qq.x), qq.y*sigmf(qq.y)};
                *(float4*)&sZ1[(r0+i)*132+c0] = make_float4(p.x,p.y,qq.x,qq.y);
                *(float4*)&sX1[(r0+i)*132+c0] = make_float4(xv[0],xv[1],xv[2],xv[3]);
                float wv = sWt[ro+r0+i];
#pragma unroll
                for (int j = 0; j < 4; j++) px[j] += wv*xv[j];
            }
            *(float4*)&pXm[rg*128+c0] = make_float4(px[0],px[1],px[2],px[3]);
            if (t < 256){
                int i0 = (t>>6)*8, dd = t&63;
                float s = 0.0f;
#pragma unroll
                for (int j = 0; j < 8; j++) s += sWt[ro+i0+j]*kcb[(i0+j)*68+dd];
                pKm[(t>>6)*64+dd] = s;
            }
        }
        __syncwarp();

        // ---- C: g0 = X1@W2 - vc -> sG; fold pW2 ----
        {
            ull acc[2] = {};
            for (int cc = 0; cc < DMM; cc += 4){
                float4 a0 = *(const float4*)&sX1[(r0+0)*132+cc];
                float4 a1 = *(const float4*)&sX1[(r0+1)*132+cc];
#pragma unroll
                for (int u = 0; u < 4; u++){
                    ull bv = *(const ull*)&sW2[(cc+u)*68+c2];
                    float e0 = u==0?a0.x:u==1?a0.y:u==2?a0.z:a0.w;
                    float e1 = u==0?a1.x:u==1?a1.y:u==2?a1.z:a1.w;
                    FMA2(acc[0],dup2(e0),bv); FMA2(acc[1],dup2(e1),bv);
                }
            }
            float pw[2] = {0,0};
#pragma unroll
            for (int i = 0; i < 2; i++){
                float2 p = unp(acc[i]);
                float g0 = p.x - vcr[i][0], g1 = p.y - vcr[i][1];
                *(float2*)&sG[(r0+i)*68+c2] = make_float2(g0, g1);
                float wl = sWs[ro+r0+i] * (-sLr[ro+r0+i]);
                pw[0] += wl*g0; pw[1] += wl*g1;
            }
            *(float2*)&pW2[rg*64+c2] = make_float2(pw[0], pw[1]);
        }
        __syncwarp();

        // ---- E: gZ1 = -lr*(g0@W2^T)*silu_bwd(Z1); fold pW1 ----
        {
            ull acc[2][2] = {};
            for (int d = 0; d < DD; d++){
                ull a0 = dup2(sG[(r0+0)*68+d]), a1 = dup2(sG[(r0+1)*68+d]);
                ulonglong2 bv = *(const ulonglong2*)&sW2T[d*132+c0];
                FMA2(acc[0][0],a0,bv.x); FMA2(acc[0][1],a0,bv.y);
                FMA2(acc[1][0],a1,bv.x); FMA2(acc[1][1],a1,bv.y);
            }
            float pw[4] = {0,0,0,0};
#pragma unroll
            for (int i = 0; i < 2; i++){
                float nlr = -sLr[ro+r0+i];
                float ws = sWs[ro+r0+i];
                float2 p = unp(acc[i][0]), qq = unp(acc[i][1]);
                float g[4] = {p.x,p.y,qq.x,qq.y};
#pragma unroll
                for (int j = 0; j < 4; j++){
                    float z = sZ1[(r0+i)*132+c0+j];
                    float sg = sigmf(z);
                    pw[j] += ws * (nlr*g[j]*(sg*(1.0f + z*(1.0f - sg))));
                }
            }
            *(float4*)&pW1[rg*128+c0] = make_float4(pw[0],pw[1],pw[2],pw[3]);
        }
        __syncthreads();

        // ---- R1: local reduce -> exch ----
        if (t < 384){
            float s = 0.0f;
            if (t < 128){
#pragma unroll
                for (int g = 0; g < 16; g++) s += pXm[g*128+t];
            } else if (t < 192){
                int d = t-128;
#pragma unroll
                for (int g = 0; g < 4; g++) s += pKm[g*64+d];
            } else if (t < 320){
                int c = t-192;
#pragma unroll
                for (int g = 0; g < 16; g++) s += pW1[g*128+c];
            } else {
                int d = t-320;
#pragma unroll
                for (int g = 0; g < 16; g++) s += pW2[g*64+d];
            }
            exch[par*384 + t] = s;
        }
        asm volatile("barrier.cluster.arrive.aligned;" ::: "memory");
        asm volatile("barrier.cluster.wait.aligned;" ::: "memory");

        // ---- R2: cross-CTA sum, update carries ----
        if (t < 384){
            float ov = exch[par*384 + t];
            float pv = ld_peer(exc_base + (uint32_t)(par*384 + t)*4u, prank);
            float v0 = (rank == 0) ? ov : pv;
            float v1 = (rank == 0) ? pv : ov;
            float total = v0 + v1;
            float m0 = lw[192], m1 = lw[193];
            if (t < 128)       sXm[t]      = m0*sXm[t]      + total;
            else if (t < 192)  sKm[t-128]  = m0*sKm[t-128]  + total;
            else if (t < 320)  sW1s[t-192] = m1*sW1s[t-192] + total;
            else               sW2s[t-320] = m1*sW2s[t-320] + total;
        }
        __syncthreads();

        // ---- G2: prefetch next chunk; W updates ----
        {
            if (ch+1 < NCH) PF(ch+1);
            float mp = lw[192];
            for (int e = t; e < DD*DMM; e += 512){
                int d = e>>7, c = e&127;
                sW1[d*132+c] = mp*sW1[d*132+c] + sKm[d]*sW1s[c];
            }
            for (int e = t; e < DMM*DD; e += 512){
                int c = e>>6, d = e&63;
                float v = mp*sW2[c*68+d] + sXm[c]*sW2s[d];
                sW2[c*68+d] = v; sW2T[d*132+c] = v;
            }
        }
        __syncthreads();

        // ---- H: Zq = qc@W1n ; silu -> sZ1 ----
        {
            ull acc[2][2] = {};
            for (int d = 0; d < DD; d += 2){
                float2 a0 = *(const float2*)&qcb[r0*68+d];
                float2 a1 = *(const float2*)&qcb[(r0+1)*68+d];
                ulonglong2 b0 = *(const ulonglong2*)&sW1[d*132+c0];
                ulonglong2 b1 = *(const ulonglong2*)&sW1[(d+1)*132+c0];
                FMA2(acc[0][0],dup2(a0.x),b0.x); FMA2(acc[0][1],dup2(a0.x),b0.y);
                FMA2(acc[1][0],dup2(a1.x),b0.x); FMA2(acc[1][1],dup2(a1.x),b0.y);
                FMA2(acc[0][0],dup2(a0.y),b1.x); FMA2(acc[0][1],dup2(a0.y),b1.y);
                FMA2(acc[1][0],dup2(a1.y),b1.x); FMA2(acc[1][1],dup2(a1.y),b1.y);
            }
#pragma unroll
            for (int i = 0; i < 2; i++){
                float2 p = unp(acc[i][0]), qq = unp(acc[i][1]);
                *(float4*)&sZ1[(r0+i)*132+c0] =
                    make_float4(p.x*sigmf(p.x), p.y*sigmf(p.y), qq.x*sigmf(qq.x), qq.y*sigmf(qq.y));
            }
        }
        __syncwarp();

        // ---- I: y = silu(Zq)@W2n -> sG ----
        {
            ull acc[2] = {};
            for (int cc = 0; cc < DMM; cc += 4){
                float4 a0 = *(const float4*)&sZ1[(r0+0)*132+cc];
                float4 a1 = *(const float4*)&sZ1[(r0+1)*132+cc];
#pragma unroll
                for (int u = 0; u < 4; u++){
                    ull bv = *(const ull*)&sW2[(cc+u)*68+c2];
                    float e0 = u==0?a0.x:u==1?a0.y:u==2?a0.z:a0.w;
                    float e1 = u==0?a1.x:u==1?a1.y:u==2?a1.z:a1.w;
                    FMA2(acc[0],dup2(e0),bv); FMA2(acc[1],dup2(e1),bv);
                }
            }
#pragma unroll
            for (int i = 0; i < 2; i++){
                float2 p = unp(acc[i]);
                *(float2*)&sG[(r0+i)*68+c2] = make_float2(p.x, p.y);
            }
        }
        __syncthreads();

        // ---- store own rows ----
        for (int e = t; e < 32*64; e += 512){
            int d = e>>5, i = e&31;
            out[(size_t)b*LL*HIDN + ((size_t)(h*DD+d))*LL + (l0+ro+i)] = sG[i*68+d];
        }
        CPW(0);
        __syncthreads();
    }
#undef PF
}

// ---------------- launch ----------------
extern "C" void kernel_launch(void* const* d_in, const int* in_sizes, int n_in,
                              void* d_out, int out_size) {
    (void)in_sizes; (void)n_in; (void)out_size;
    const float* X   = (const float*)d_in[0];
    const float* Wq  = (const float*)d_in[1];
    const float* Wk  = (const float*)d_in[2];
    const float* Wv  = (const float*)d_in[3];
    const float* cqw = (const float*)d_in[4];
    const float* cqb = (const float*)d_in[5];
    const float* ckw = (const float*)d_in[6];
    const float* ckb = (const float*)d_in[7];
    const float* cvw = (const float*)d_in[8];
    const float* cvb = (const float*)d_in[9];
    const float* qnw = (const float*)d_in[10];
    const float* knw = (const float*)d_in[11];
    const float* mdw = (const float*)d_in[12];
    const float* mdb = (const float*)d_in[13];
    const float* sw  = (const float*)d_in[14];
    const float* sb  = (const float*)d_in[15];
    const float* lw  = (const float*)d_in[16];
    const float* lb  = (const float*)d_in[17];
    const float* W1g = (const float*)d_in[18];
    const float* W2g = (const float*)d_in[19];
    float* out = (float*)d_out;

    cudaFuncSetAttribute(k_qkv, cudaFuncAttributeMaxDynamicSharedMemorySize, QSMEM);
    cudaFuncSetAttribute(k_scan, cudaFuncAttributeMaxDynamicSharedMemorySize, SCAN_BYTES);

    __half *xhi, *xlo, *whi;
    cudaGetSymbolAddress((void**)&xhi, g_Xhi);
    cudaGetSymbolAddress((void**)&xlo, g_Xlo);
    cudaGetSymbolAddress((void**)&whi, g_Whi);

    k_splitA<<<MM*HIDN/1024, 256>>>(X, xhi, xlo, MM*HIDN);
    k_cvtW<<<HIDN*HIDN/1024, 256>>>(Wq, whi, HIDN*HIDN);
    k_cvtW<<<HIDN*HIDN/1024, 256>>>(Wk, whi + (size_t)HIDN*HIDN, HIDN*HIDN);
    k_cvtW<<<HIDN*HIDN/1024, 256>>>(Wv, whi + (size_t)2*HIDN*HIDN, HIDN*HIDN);
    k_qkv<<<dim3(HIDN/128, MM/128, 3), 256, QSMEM>>>();
    k_gate<<<dim3(MM/64), 256>>>(X, mdw, mdb, sw, sb, lw, lb);
    k_conv<<<dim3(LL/CT, BB, 3), 256>>>(cqw, cqb, ckw, ckb, cvw, cvb, qnw, knw);
    k_scan<<<dim3(BB*HH*2), 512, SCAN_BYTES>>>(W1g, W2g, out);
}